// round 8
// baseline (speedup 1.0000x reference)
#include <cuda_runtime.h>
#include <cstdint>

// ============================================================================
// TiLinear hybrid v3 (persistent, rebalanced): int8 GEMM (8192x4096x4096).
//   warps 0-7 : mma.sync m16n8k32 IMMA, k-tiles [0,11)   (3-stage ring, +2 la)
//   warps 8-15: dp4a on the fma pipe,  k-tiles [11,32)   (2-stage ring, +1 la)
// Measured rates (R7 ncu): IMMA ~280 MACs/cyc/SM, dp4a ~512 MACs/cyc/SM
// -> optimal K split ~11/21 (was 17/15).
// 148 persistent CTAs; rings run continuously across tiles; dedicated smem
// partial buffer; combine + C32 store + max overlap next tile's mainloop.
// ============================================================================

#define M_DIM 8192
#define N_DIM 4096
#define K_DIM 4096
#define BITWIDTH 7

#define NTILES_TOTAL 2048
#define GRID_P 148

#define KTILES 32
#define NKT_T 11
#define NKT_D (KTILES - NKT_T)   // 21
#define TILE_BYTES 16384          // 128x128 int8
#define STAGE_BYTES 32768         // A tile + B tile
#define NST_T 3
#define NST_D 2
#define TPOOL_OFF 0
#define DPOOL_OFF (NST_T * STAGE_BYTES)                  // 98304
#define PART_OFF  (DPOOL_OFF + NST_D * STAGE_BYTES)      // 163840
#define CTRL_OFF  (PART_OFF + 65536)                     // 229376
#define SMEM_DYN  (CTRL_OFF + 128)                       // 229504

__device__ __align__(128) int8_t g_A8[(size_t)M_DIM * K_DIM];   // 32 MB
__device__ __align__(128) int8_t g_B8[(size_t)N_DIM * K_DIM];   // 16 MB
__device__ __align__(16)  int    g_C32[(size_t)M_DIM * N_DIM];  // 128 MB
__device__ int g_max;

// ----------------------------------------------------------------------------
__global__ void zero_max_kernel() {
    if (threadIdx.x == 0) g_max = 0;
}

// A tiles: block = kt*64 + (m>>7); 128x128; chunk-XOR swizzled rows.
__global__ void __launch_bounds__(256) pack_a_kernel(const int* __restrict__ src) {
    unsigned i = blockIdx.x * 256u + threadIdx.x;
    unsigned lc = i & 7u;
    unsigned m  = (i >> 3) & 8191u;
    unsigned kt = i >> 16;
    const int4* s = (const int4*)(src + (size_t)m * K_DIM + kt * 128 + lc * 16);
    uint32_t w[4];
#pragma unroll
    for (int j = 0; j < 4; ++j) {
        int4 v = s[j];
        w[j] = (uint32_t)(v.x & 0xff) | ((uint32_t)(v.y & 0xff) << 8) |
               ((uint32_t)(v.z & 0xff) << 16) | ((uint32_t)(v.w & 0xff) << 24);
    }
    unsigned lr = m & 127u;
    size_t base = (size_t)(kt * 64 + (m >> 7)) * TILE_BYTES;
    size_t off  = base + lr * 128 + (((lc ^ lr) & 7u) << 4);
    *(uint4*)(g_A8 + off) = make_uint4(w[0], w[1], w[2], w[3]);
}

// B tiles: block = kt*32 + (n>>7).
__global__ void __launch_bounds__(256) pack_b_kernel(const int* __restrict__ src) {
    unsigned i = blockIdx.x * 256u + threadIdx.x;
    unsigned lc = i & 7u;
    unsigned n  = (i >> 3) & 4095u;
    unsigned kt = i >> 15;
    const int4* s = (const int4*)(src + (size_t)n * K_DIM + kt * 128 + lc * 16);
    uint32_t w[4];
#pragma unroll
    for (int j = 0; j < 4; ++j) {
        int4 v = s[j];
        w[j] = (uint32_t)(v.x & 0xff) | ((uint32_t)(v.y & 0xff) << 8) |
               ((uint32_t)(v.z & 0xff) << 16) | ((uint32_t)(v.w & 0xff) << 24);
    }
    unsigned lr = n & 127u;
    size_t base = (size_t)(kt * 32 + (n >> 7)) * TILE_BYTES;
    size_t off  = base + lr * 128 + (((lc ^ lr) & 7u) << 4);
    *(uint4*)(g_B8 + off) = make_uint4(w[0], w[1], w[2], w[3]);
}

// ----------------------------------------------------------------------------
__device__ __forceinline__ void mbar_init(uint32_t a, uint32_t cnt) {
    asm volatile("mbarrier.init.shared.b64 [%0], %1;" :: "r"(a), "r"(cnt) : "memory");
}
__device__ __forceinline__ void mbar_expect_tx(uint32_t a, uint32_t bytes) {
    asm volatile("mbarrier.arrive.expect_tx.shared.b64 _, [%0], %1;"
                 :: "r"(a), "r"(bytes) : "memory");
}
__device__ __forceinline__ void mbar_arrive(uint32_t a) {
    asm volatile("mbarrier.arrive.shared.b64 _, [%0];" :: "r"(a) : "memory");
}
__device__ __forceinline__ void mbar_wait(uint32_t a, uint32_t parity) {
    asm volatile(
        "{\n\t.reg .pred P;\n\t"
        "WAIT_%=:\n\t"
        "mbarrier.try_wait.parity.acquire.cta.shared::cta.b64 P, [%0], %1, 0x989680;\n\t"
        "@P bra.uni DONE_%=;\n\t"
        "bra.uni WAIT_%=;\n\t"
        "DONE_%=:\n\t}"
        :: "r"(a), "r"(parity) : "memory");
}
__device__ __forceinline__ void bulk_g2s(uint32_t dst, const void* src,
                                         uint32_t bytes, uint32_t mbar) {
    asm volatile(
        "cp.async.bulk.shared::cluster.global.mbarrier::complete_tx::bytes "
        "[%0], [%1], %2, [%3];"
        :: "r"(dst), "l"(src), "r"(bytes), "r"(mbar) : "memory");
}
__device__ __forceinline__ uint32_t swz_off(uint32_t row, uint32_t chunk) {
    return row * 128u + (((chunk ^ row) & 7u) << 4);
}
__device__ __forceinline__ void bar_sync(int id, int cnt) {
    asm volatile("bar.sync %0, %1;" :: "r"(id), "r"(cnt) : "memory");
}
__device__ __forceinline__ void fill_blocks(uint32_t dst, uint32_t mbar,
                                            int ablk, int bblk) {
    mbar_expect_tx(mbar, STAGE_BYTES);
    bulk_g2s(dst, g_A8 + (size_t)ablk * TILE_BYTES, TILE_BYTES, mbar);
    bulk_g2s(dst + TILE_BYTES, g_B8 + (size_t)bblk * TILE_BYTES, TILE_BYTES, mbar);
}

// ----------------------------------------------------------------------------
__global__ void __launch_bounds__(512, 1) gemm_persist_kernel() {
    extern __shared__ __align__(1024) int8_t smem[];
    __shared__ int s_bmax;
    const int tid  = threadIdx.x;
    const int lane = tid & 31;
    const int warp = tid >> 5;
    const int bid  = blockIdx.x;
    const int ntiles = (NTILES_TOTAL - 1 - bid) / GRID_P + 1;
    const uint32_t sbase = (uint32_t)__cvta_generic_to_shared(smem);
    const uint32_t mbT = sbase + CTRL_OFF;          // 3 pairs (full, empty)
    const uint32_t mbD = sbase + CTRL_OFF + 48;     // 2 pairs

    if (tid == 0) {
        s_bmax = 0;
#pragma unroll
        for (int s = 0; s < NST_T; ++s) {
            mbar_init(mbT + s * 16 + 0, 1);
            mbar_init(mbT + s * 16 + 8, 256);
        }
#pragma unroll
        for (int s = 0; s < NST_D; ++s) {
            mbar_init(mbD + s * 16 + 0, 1);
            mbar_init(mbD + s * 16 + 8, 256);
        }
        asm volatile("fence.mbarrier_init.release.cluster;" ::: "memory");
    }
    __syncthreads();

    if (warp < 8) {
        // ==================== TENSOR GROUP ====================
        const int wm = warp >> 2, wn = warp & 3;
        const int total = ntiles * NKT_T;
        int cs = 0, cp = 0;        // consumer cursor
        int ps = 0, pp = 1;        // producer cursor (fresh empty passes at 1)

        auto t_fill = [&](int f) {
            int li = f / NKT_T;
            int kt = f - li * NKT_T;
            int tile = bid + li * GRID_P;
            mbar_wait(mbT + ps * 16 + 8, pp);
            fill_blocks(sbase + TPOOL_OFF + ps * STAGE_BYTES, mbT + ps * 16,
                        kt * 64 + (tile >> 5), kt * 32 + (tile & 31));
            if (++ps == NST_T) { ps = 0; pp ^= 1; }
        };

        if (tid == 0) { t_fill(0); if (total > 1) t_fill(1); }

        for (int li = 0; li < ntiles; ++li) {
            int acc[4][4][4];
#pragma unroll
            for (int a = 0; a < 4; ++a)
#pragma unroll
                for (int b = 0; b < 4; ++b)
#pragma unroll
                    for (int c = 0; c < 4; ++c) acc[a][b][c] = 0;

#pragma unroll 1
            for (int k = 0; k < NKT_T; ++k) {
                if (tid == 0) {
                    int f = li * NKT_T + k + 2;
                    if (f < total) t_fill(f);
                }
                mbar_wait(mbT + cs * 16, cp);

                const int8_t* sa = smem + TPOOL_OFF + cs * STAGE_BYTES;
                const int8_t* sb = sa + TILE_BYTES;
#pragma unroll
                for (int ks = 0; ks < 4; ++ks) {
                    uint32_t afr[4][4];
#pragma unroll
                    for (int mi = 0; mi < 4; ++mi) {
                        int r = wm * 64 + mi * 16 + (lane & 15);
                        int c = ks * 2 + (lane >> 4);
                        uint32_t addr =
                            (uint32_t)__cvta_generic_to_shared(sa + swz_off(r, c));
                        asm volatile(
                            "ldmatrix.sync.aligned.m8n8.x4.shared.b16 "
                            "{%0,%1,%2,%3}, [%4];\n"
                            : "=r"(afr[mi][0]), "=r"(afr[mi][1]),
                              "=r"(afr[mi][2]), "=r"(afr[mi][3])
                            : "r"(addr));
                    }
                    uint32_t bfr[4][2];
#pragma unroll
                    for (int ni = 0; ni < 4; ++ni) {
                        int r = wn * 32 + ni * 8 + (lane & 7);
                        int c = ks * 2 + ((lane >> 3) & 1);
                        uint32_t addr =
                            (uint32_t)__cvta_generic_to_shared(sb + swz_off(r, c));
                        asm volatile(
                            "ldmatrix.sync.aligned.m8n8.x2.shared.b16 {%0,%1}, [%2];\n"
                            : "=r"(bfr[ni][0]), "=r"(bfr[ni][1])
                            : "r"(addr));
                    }
#pragma unroll
                    for (int mi = 0; mi < 4; ++mi)
#pragma unroll
                        for (int ni = 0; ni < 4; ++ni) {
                            asm volatile(
                                "mma.sync.aligned.m16n8k32.row.col.s32.s8.s8.s32 "
                                "{%0,%1,%2,%3}, {%4,%5,%6,%7}, {%8,%9}, {%0,%1,%2,%3};\n"
                                : "+r"(acc[mi][ni][0]), "+r"(acc[mi][ni][1]),
                                  "+r"(acc[mi][ni][2]), "+r"(acc[mi][ni][3])
                                : "r"(afr[mi][0]), "r"(afr[mi][1]),
                                  "r"(afr[mi][2]), "r"(afr[mi][3]),
                                  "r"(bfr[ni][0]), "r"(bfr[ni][1]));
                        }
                }
                mbar_arrive(mbT + cs * 16 + 8);
                if (++cs == NST_T) { cs = 0; cp ^= 1; }
            }

            // Y barrier: dp4a finished reading the previous tile's partials
            bar_sync(3, 512);
            int* pbuf = (int*)(smem + PART_OFF);
#pragma unroll
            for (int mi = 0; mi < 4; ++mi)
#pragma unroll
                for (int ni = 0; ni < 4; ++ni) {
                    int r = wm * 64 + mi * 16 + (lane >> 2);
                    int c = wn * 32 + ni * 8 + (lane & 3) * 2;
                    *(int2*)&pbuf[r * 128 + c] =
                        make_int2(acc[mi][ni][0], acc[mi][ni][1]);
                    *(int2*)&pbuf[(r + 8) * 128 + c] =
                        make_int2(acc[mi][ni][2], acc[mi][ni][3]);
                }
            // X barrier: partials ready for this tile
            bar_sync(3, 512);
        }
    } else {
        // ==================== DP4A GROUP ====================
        const int wd = warp - 8;
        const int mg = lane >> 4;
        const int ng = lane & 15;
        const int rowA0 = 16 * wd + 8 * mg;
        const int total = ntiles * NKT_D;
        int cs = 0, cp = 0;
        int ps = 0, pp = 1;
        int lmax = 0;

        auto d_fill = [&](int f) {
            int li = f / NKT_D;
            int kd = f - li * NKT_D;
            int tile = bid + li * GRID_P;
            mbar_wait(mbD + ps * 16 + 8, pp);
            fill_blocks(sbase + DPOOL_OFF + ps * STAGE_BYTES, mbD + ps * 16,
                        (NKT_T + kd) * 64 + (tile >> 5),
                        (NKT_T + kd) * 32 + (tile & 31));
            if (++ps == NST_D) { ps = 0; pp ^= 1; }
        };

        // 2-stage ring: prefill exactly ONE stage, +1 lookahead.
        if (tid == 256) d_fill(0);

        for (int li = 0; li < ntiles; ++li) {
            const int tile = bid + li * GRID_P;
            const int m0 = (tile >> 5) * 128;
            const int n0 = (tile & 31) * 128;

            int accD[64];
#pragma unroll
            for (int j = 0; j < 64; ++j) accD[j] = 0;

#pragma unroll 1
            for (int k = 0; k < NKT_D; ++k) {
                if (tid == 256) {
                    int f = li * NKT_D + k + 1;   // +1 lookahead only
                    if (f < total) d_fill(f);
                }
                mbar_wait(mbD + cs * 16, cp);

                const int8_t* sa = smem + DPOOL_OFF + cs * STAGE_BYTES;
                const int8_t* sb = sa + TILE_BYTES;
#pragma unroll 1
                for (int cc = 0; cc < 8; ++cc) {
                    const int ch = (cc + ng) & 7;
                    int4 a[8];
#pragma unroll
                    for (int i = 0; i < 8; ++i)
                        a[i] = *(const int4*)(sa + (rowA0 + i) * 128 + ((ch ^ i) << 4));
#pragma unroll
                    for (int nj = 0; nj < 8; ++nj) {
                        int4 b = *(const int4*)(sb + (8 * ng + nj) * 128 +
                                                ((ch ^ nj) << 4));
#pragma unroll
                        for (int i = 0; i < 8; ++i) {
                            int t = __dp4a(a[i].x, b.x, accD[i * 8 + nj]);
                            t = __dp4a(a[i].y, b.y, t);
                            t = __dp4a(a[i].z, b.z, t);
                            accD[i * 8 + nj] = __dp4a(a[i].w, b.w, t);
                        }
                    }
                }
                mbar_arrive(mbD + cs * 16 + 8);
                if (++cs == NST_D) { cs = 0; cp ^= 1; }
            }

            bar_sync(3, 512);   // Y
            bar_sync(3, 512);   // X: partials ready
            // combine (overlaps tensor's next-tile mainloop)
            const int* pbuf = (const int*)(smem + PART_OFF);
#pragma unroll
            for (int i = 0; i < 8; ++i) {
                int r = rowA0 + i;
                int4 p0 = *(const int4*)&pbuf[r * 128 + 8 * ng];
                int4 p1 = *(const int4*)&pbuf[r * 128 + 8 * ng + 4];
                int v0 = p0.x + accD[i * 8 + 0];
                int v1 = p0.y + accD[i * 8 + 1];
                int v2 = p0.z + accD[i * 8 + 2];
                int v3 = p0.w + accD[i * 8 + 3];
                int v4 = p1.x + accD[i * 8 + 4];
                int v5 = p1.y + accD[i * 8 + 5];
                int v6 = p1.z + accD[i * 8 + 6];
                int v7 = p1.w + accD[i * 8 + 7];
                lmax = max(lmax, abs(v0)); lmax = max(lmax, abs(v1));
                lmax = max(lmax, abs(v2)); lmax = max(lmax, abs(v3));
                lmax = max(lmax, abs(v4)); lmax = max(lmax, abs(v5));
                lmax = max(lmax, abs(v6)); lmax = max(lmax, abs(v7));
                int* dst = g_C32 + (size_t)(m0 + r) * N_DIM + n0 + 8 * ng;
                *(int4*)dst       = make_int4(v0, v1, v2, v3);
                *(int4*)(dst + 4) = make_int4(v4, v5, v6, v7);
            }
        }

#pragma unroll
        for (int o = 16; o > 0; o >>= 1)
            lmax = max(lmax, __shfl_xor_sync(0xffffffffu, lmax, o));
        if (lane == 0) atomicMax(&s_bmax, lmax);
        bar_sync(2, 256);
        if (tid == 256) atomicMax(&g_max, s_bmax);
    }
}

// ----------------------------------------------------------------------------
__device__ __forceinline__ int compute_eff() {
    int m = g_max;
    if (m == 0) return 0;
    float mf = (float)m;
    unsigned bits = __float_as_uint(mf);
    int e  = (int)((bits >> 23) & 0xff) - 127;
    int bw = e + ((bits & 0x7fffffu) ? 1 : 0);
    int shift = bw - BITWIDTH;
    return shift > 1 ? shift : (shift == 1 ? 2 : 0);
}

__device__ __forceinline__ int psto_one(int x, int s) {
    int rt   = x >> s;
    int prob = x & ((1 << s) - 1);
    int h    = s >> 1;
    int qp   = prob >> h;
    int prn  = prob & ((1 << h) - 1);
    if (s & 1) prn <<= 1;
    int sgn = (x > 0) - (x < 0);
    int dec = (qp <= prn) ? 0 : sgn;
    int o = rt + dec;
    o = o > 127 ? 127 : (o < -127 ? -127 : o);
    return o;
}

__global__ void __launch_bounds__(256) epilogue_kernel(float* __restrict__ out) {
    const int eff = compute_eff();
    size_t i = (size_t)blockIdx.x * blockDim.x + threadIdx.x;
    int4 v = ((const int4*)g_C32)[i];
    float4 o;
    if (eff > 0) {
        o.x = (float)psto_one(v.x, eff);
        o.y = (float)psto_one(v.y, eff);
        o.z = (float)psto_one(v.z, eff);
        o.w = (float)psto_one(v.w, eff);
    } else {
        o.x = (float)(int8_t)(v.x);
        o.y = (float)(int8_t)(v.y);
        o.z = (float)(int8_t)(v.z);
        o.w = (float)(int8_t)(v.w);
    }
    ((float4*)out)[i] = o;
}

__global__ void tail_kernel(float* __restrict__ out, long long start, long long count,
                            const int* __restrict__ e1, const int* __restrict__ e2) {
    int eff = compute_eff();
    int8_t ev = (int8_t)(e1[0] + e2[0] + eff);
    for (long long i = threadIdx.x; i < count; i += blockDim.x)
        out[start + i] = (float)ev;
}

// ----------------------------------------------------------------------------
extern "C" void kernel_launch(void* const* d_in, const int* in_sizes, int n_in,
                              void* d_out, int out_size) {
    const int* act   = (const int*)d_in[0];
    const int* expin = (const int*)d_in[1];
    const int* wgt   = (const int*)d_in[2];
    const int* wexp  = (const int*)d_in[3];
    float* out = (float*)d_out;
    (void)in_sizes; (void)n_in;

    cudaFuncSetAttribute(gemm_persist_kernel,
                         cudaFuncAttributeMaxDynamicSharedMemorySize, SMEM_DYN);

    zero_max_kernel<<<1, 32>>>();
    pack_a_kernel<<<8192, 256>>>(act);
    pack_b_kernel<<<4096, 256>>>(wgt);

    gemm_persist_kernel<<<GRID_P, 512, SMEM_DYN>>>();

    long long total = (long long)M_DIM * N_DIM;
    epilogue_kernel<<<(int)(total / 4 / 256), 256>>>(out);
    long long tail = (long long)out_size - total;
    if (tail > 0) tail_kernel<<<1, 32>>>(out, total, tail, expin, wexp);
}

// round 9
// speedup vs baseline: 1.0840x; 1.0840x over previous
#include <cuda_runtime.h>
#include <cstdint>

// ============================================================================
// TiLinear hybrid v4 (persistent): int8 GEMM (8192x4096x4096) on BOTH pipes.
//   warps 0-7 : mma.sync m16n8k32 IMMA, k-tiles [0,13)   (3-stage ring, +2 la)
//   warps 8-15: dp4a on the fma pipe,  k-tiles [13,32)   (2-stage ring, +1 la)
// vs R8: dp4a B-column remap (thread ng owns cols 16j+ng) kills the 8-way
// smem bank conflict on B loads; B register double-buffering hides LDS
// latency; split retuned 13/19 for measured rates (IMMA 7.4k, dp4a ~5k
// cyc/ktile/SMSP).
// ============================================================================

#define M_DIM 8192
#define N_DIM 4096
#define K_DIM 4096
#define BITWIDTH 7

#define NTILES_TOTAL 2048
#define GRID_P 148

#define KTILES 32
#define NKT_T 13
#define NKT_D (KTILES - NKT_T)   // 19
#define TILE_BYTES 16384          // 128x128 int8
#define STAGE_BYTES 32768         // A tile + B tile
#define NST_T 3
#define NST_D 2
#define TPOOL_OFF 0
#define DPOOL_OFF (NST_T * STAGE_BYTES)                  // 98304
#define PART_OFF  (DPOOL_OFF + NST_D * STAGE_BYTES)      // 163840
#define CTRL_OFF  (PART_OFF + 65536)                     // 229376
#define SMEM_DYN  (CTRL_OFF + 128)                       // 229504

__device__ __align__(128) int8_t g_A8[(size_t)M_DIM * K_DIM];   // 32 MB
__device__ __align__(128) int8_t g_B8[(size_t)N_DIM * K_DIM];   // 16 MB
__device__ __align__(16)  int    g_C32[(size_t)M_DIM * N_DIM];  // 128 MB
__device__ int g_max;

// ----------------------------------------------------------------------------
__global__ void zero_max_kernel() {
    if (threadIdx.x == 0) g_max = 0;
}

// A tiles: block = kt*64 + (m>>7); 128x128; chunk-XOR swizzled rows.
__global__ void __launch_bounds__(256) pack_a_kernel(const int* __restrict__ src) {
    unsigned i = blockIdx.x * 256u + threadIdx.x;
    unsigned lc = i & 7u;
    unsigned m  = (i >> 3) & 8191u;
    unsigned kt = i >> 16;
    const int4* s = (const int4*)(src + (size_t)m * K_DIM + kt * 128 + lc * 16);
    uint32_t w[4];
#pragma unroll
    for (int j = 0; j < 4; ++j) {
        int4 v = s[j];
        w[j] = (uint32_t)(v.x & 0xff) | ((uint32_t)(v.y & 0xff) << 8) |
               ((uint32_t)(v.z & 0xff) << 16) | ((uint32_t)(v.w & 0xff) << 24);
    }
    unsigned lr = m & 127u;
    size_t base = (size_t)(kt * 64 + (m >> 7)) * TILE_BYTES;
    size_t off  = base + lr * 128 + (((lc ^ lr) & 7u) << 4);
    *(uint4*)(g_A8 + off) = make_uint4(w[0], w[1], w[2], w[3]);
}

// B tiles: block = kt*32 + (n>>7).
__global__ void __launch_bounds__(256) pack_b_kernel(const int* __restrict__ src) {
    unsigned i = blockIdx.x * 256u + threadIdx.x;
    unsigned lc = i & 7u;
    unsigned n  = (i >> 3) & 4095u;
    unsigned kt = i >> 15;
    const int4* s = (const int4*)(src + (size_t)n * K_DIM + kt * 128 + lc * 16);
    uint32_t w[4];
#pragma unroll
    for (int j = 0; j < 4; ++j) {
        int4 v = s[j];
        w[j] = (uint32_t)(v.x & 0xff) | ((uint32_t)(v.y & 0xff) << 8) |
               ((uint32_t)(v.z & 0xff) << 16) | ((uint32_t)(v.w & 0xff) << 24);
    }
    unsigned lr = n & 127u;
    size_t base = (size_t)(kt * 32 + (n >> 7)) * TILE_BYTES;
    size_t off  = base + lr * 128 + (((lc ^ lr) & 7u) << 4);
    *(uint4*)(g_B8 + off) = make_uint4(w[0], w[1], w[2], w[3]);
}

// ----------------------------------------------------------------------------
__device__ __forceinline__ void mbar_init(uint32_t a, uint32_t cnt) {
    asm volatile("mbarrier.init.shared.b64 [%0], %1;" :: "r"(a), "r"(cnt) : "memory");
}
__device__ __forceinline__ void mbar_expect_tx(uint32_t a, uint32_t bytes) {
    asm volatile("mbarrier.arrive.expect_tx.shared.b64 _, [%0], %1;"
                 :: "r"(a), "r"(bytes) : "memory");
}
__device__ __forceinline__ void mbar_arrive(uint32_t a) {
    asm volatile("mbarrier.arrive.shared.b64 _, [%0];" :: "r"(a) : "memory");
}
__device__ __forceinline__ void mbar_wait(uint32_t a, uint32_t parity) {
    asm volatile(
        "{\n\t.reg .pred P;\n\t"
        "WAIT_%=:\n\t"
        "mbarrier.try_wait.parity.acquire.cta.shared::cta.b64 P, [%0], %1, 0x989680;\n\t"
        "@P bra.uni DONE_%=;\n\t"
        "bra.uni WAIT_%=;\n\t"
        "DONE_%=:\n\t}"
        :: "r"(a), "r"(parity) : "memory");
}
__device__ __forceinline__ void bulk_g2s(uint32_t dst, const void* src,
                                         uint32_t bytes, uint32_t mbar) {
    asm volatile(
        "cp.async.bulk.shared::cluster.global.mbarrier::complete_tx::bytes "
        "[%0], [%1], %2, [%3];"
        :: "r"(dst), "l"(src), "r"(bytes), "r"(mbar) : "memory");
}
__device__ __forceinline__ uint32_t swz_off(uint32_t row, uint32_t chunk) {
    return row * 128u + (((chunk ^ row) & 7u) << 4);
}
__device__ __forceinline__ void bar_sync(int id, int cnt) {
    asm volatile("bar.sync %0, %1;" :: "r"(id), "r"(cnt) : "memory");
}
__device__ __forceinline__ void fill_blocks(uint32_t dst, uint32_t mbar,
                                            int ablk, int bblk) {
    mbar_expect_tx(mbar, STAGE_BYTES);
    bulk_g2s(dst, g_A8 + (size_t)ablk * TILE_BYTES, TILE_BYTES, mbar);
    bulk_g2s(dst + TILE_BYTES, g_B8 + (size_t)bblk * TILE_BYTES, TILE_BYTES, mbar);
}

// ----------------------------------------------------------------------------
__global__ void __launch_bounds__(512, 1) gemm_persist_kernel() {
    extern __shared__ __align__(1024) int8_t smem[];
    __shared__ int s_bmax;
    const int tid  = threadIdx.x;
    const int lane = tid & 31;
    const int warp = tid >> 5;
    const int bid  = blockIdx.x;
    const int ntiles = (NTILES_TOTAL - 1 - bid) / GRID_P + 1;
    const uint32_t sbase = (uint32_t)__cvta_generic_to_shared(smem);
    const uint32_t mbT = sbase + CTRL_OFF;          // 3 pairs (full, empty)
    const uint32_t mbD = sbase + CTRL_OFF + 48;     // 2 pairs

    if (tid == 0) {
        s_bmax = 0;
#pragma unroll
        for (int s = 0; s < NST_T; ++s) {
            mbar_init(mbT + s * 16 + 0, 1);
            mbar_init(mbT + s * 16 + 8, 256);
        }
#pragma unroll
        for (int s = 0; s < NST_D; ++s) {
            mbar_init(mbD + s * 16 + 0, 1);
            mbar_init(mbD + s * 16 + 8, 256);
        }
        asm volatile("fence.mbarrier_init.release.cluster;" ::: "memory");
    }
    __syncthreads();

    if (warp < 8) {
        // ==================== TENSOR GROUP ====================
        const int wm = warp >> 2, wn = warp & 3;
        const int total = ntiles * NKT_T;
        int cs = 0, cp = 0;        // consumer cursor
        int ps = 0, pp = 1;        // producer cursor (fresh empty passes at 1)

        auto t_fill = [&](int f) {
            int li = f / NKT_T;
            int kt = f - li * NKT_T;
            int tile = bid + li * GRID_P;
            mbar_wait(mbT + ps * 16 + 8, pp);
            fill_blocks(sbase + TPOOL_OFF + ps * STAGE_BYTES, mbT + ps * 16,
                        kt * 64 + (tile >> 5), kt * 32 + (tile & 31));
            if (++ps == NST_T) { ps = 0; pp ^= 1; }
        };

        if (tid == 0) { t_fill(0); if (total > 1) t_fill(1); }

        for (int li = 0; li < ntiles; ++li) {
            int acc[4][4][4];
#pragma unroll
            for (int a = 0; a < 4; ++a)
#pragma unroll
                for (int b = 0; b < 4; ++b)
#pragma unroll
                    for (int c = 0; c < 4; ++c) acc[a][b][c] = 0;

#pragma unroll 1
            for (int k = 0; k < NKT_T; ++k) {
                if (tid == 0) {
                    int f = li * NKT_T + k + 2;
                    if (f < total) t_fill(f);
                }
                mbar_wait(mbT + cs * 16, cp);

                const int8_t* sa = smem + TPOOL_OFF + cs * STAGE_BYTES;
                const int8_t* sb = sa + TILE_BYTES;
#pragma unroll
                for (int ks = 0; ks < 4; ++ks) {
                    uint32_t afr[4][4];
#pragma unroll
                    for (int mi = 0; mi < 4; ++mi) {
                        int r = wm * 64 + mi * 16 + (lane & 15);
                        int c = ks * 2 + (lane >> 4);
                        uint32_t addr =
                            (uint32_t)__cvta_generic_to_shared(sa + swz_off(r, c));
                        asm volatile(
                            "ldmatrix.sync.aligned.m8n8.x4.shared.b16 "
                            "{%0,%1,%2,%3}, [%4];\n"
                            : "=r"(afr[mi][0]), "=r"(afr[mi][1]),
                              "=r"(afr[mi][2]), "=r"(afr[mi][3])
                            : "r"(addr));
                    }
                    uint32_t bfr[4][2];
#pragma unroll
                    for (int ni = 0; ni < 4; ++ni) {
                        int r = wn * 32 + ni * 8 + (lane & 7);
                        int c = ks * 2 + ((lane >> 3) & 1);
                        uint32_t addr =
                            (uint32_t)__cvta_generic_to_shared(sb + swz_off(r, c));
                        asm volatile(
                            "ldmatrix.sync.aligned.m8n8.x2.shared.b16 {%0,%1}, [%2];\n"
                            : "=r"(bfr[ni][0]), "=r"(bfr[ni][1])
                            : "r"(addr));
                    }
#pragma unroll
                    for (int mi = 0; mi < 4; ++mi)
#pragma unroll
                        for (int ni = 0; ni < 4; ++ni) {
                            asm volatile(
                                "mma.sync.aligned.m16n8k32.row.col.s32.s8.s8.s32 "
                                "{%0,%1,%2,%3}, {%4,%5,%6,%7}, {%8,%9}, {%0,%1,%2,%3};\n"
                                : "+r"(acc[mi][ni][0]), "+r"(acc[mi][ni][1]),
                                  "+r"(acc[mi][ni][2]), "+r"(acc[mi][ni][3])
                                : "r"(afr[mi][0]), "r"(afr[mi][1]),
                                  "r"(afr[mi][2]), "r"(afr[mi][3]),
                                  "r"(bfr[ni][0]), "r"(bfr[ni][1]));
                        }
                }
                mbar_arrive(mbT + cs * 16 + 8);
                if (++cs == NST_T) { cs = 0; cp ^= 1; }
            }

            // Y barrier: dp4a finished reading the previous tile's partials
            bar_sync(3, 512);
            int* pbuf = (int*)(smem + PART_OFF);
#pragma unroll
            for (int mi = 0; mi < 4; ++mi)
#pragma unroll
                for (int ni = 0; ni < 4; ++ni) {
                    int r = wm * 64 + mi * 16 + (lane >> 2);
                    int c = wn * 32 + ni * 8 + (lane & 3) * 2;
                    *(int2*)&pbuf[r * 128 + c] =
                        make_int2(acc[mi][ni][0], acc[mi][ni][1]);
                    *(int2*)&pbuf[(r + 8) * 128 + c] =
                        make_int2(acc[mi][ni][2], acc[mi][ni][3]);
                }
            // X barrier: partials ready for this tile
            bar_sync(3, 512);
        }
    } else {
        // ==================== DP4A GROUP ====================
        // Thread (wd, mg, ng) owns rows rowA0..rowA0+7 and columns 16j+ng.
        // B loads: row 16j+ng -> swizzle offset ((cc^ng)&7)<<4, so each
        // 8-lane LDS phase covers 8 distinct 16B banks groups: conflict-free.
        const int wd = warp - 8;
        const int mg = lane >> 4;
        const int ng = lane & 15;
        const int rowA0 = 16 * wd + 8 * mg;
        const int total = ntiles * NKT_D;
        int cs = 0, cp = 0;
        int ps = 0, pp = 1;
        int lmax = 0;

        auto d_fill = [&](int f) {
            int li = f / NKT_D;
            int kd = f - li * NKT_D;
            int tile = bid + li * GRID_P;
            mbar_wait(mbD + ps * 16 + 8, pp);
            fill_blocks(sbase + DPOOL_OFF + ps * STAGE_BYTES, mbD + ps * 16,
                        (NKT_T + kd) * 64 + (tile >> 5),
                        (NKT_T + kd) * 32 + (tile & 31));
            if (++ps == NST_D) { ps = 0; pp ^= 1; }
        };

        // 2-stage ring: prefill exactly ONE stage, +1 lookahead.
        if (tid == 256) d_fill(0);

        for (int li = 0; li < ntiles; ++li) {
            const int tile = bid + li * GRID_P;
            const int m0 = (tile >> 5) * 128;
            const int n0 = (tile & 31) * 128;

            int accD[64];
#pragma unroll
            for (int j = 0; j < 64; ++j) accD[j] = 0;

#pragma unroll 1
            for (int k = 0; k < NKT_D; ++k) {
                if (tid == 256) {
                    int f = li * NKT_D + k + 1;   // +1 lookahead only
                    if (f < total) d_fill(f);
                }
                mbar_wait(mbD + cs * 16, cp);

                const int8_t* sa = smem + DPOOL_OFF + cs * STAGE_BYTES;
                const int8_t* sb = sa + TILE_BYTES;
#pragma unroll 1
                for (int cc = 0; cc < 8; ++cc) {
                    int4 a[8];
#pragma unroll
                    for (int i = 0; i < 8; ++i) {
                        int r = rowA0 + i;
                        a[i] = *(const int4*)(sa + r * 128 + (((cc ^ r) & 7) << 4));
                    }
                    const int boff = ((cc ^ ng) & 7) << 4;
                    int4 b = *(const int4*)(sb + ng * 128 + boff);
#pragma unroll
                    for (int j = 0; j < 8; ++j) {
                        int4 bn;
                        if (j < 7)
                            bn = *(const int4*)(sb + (16 * (j + 1) + ng) * 128 + boff);
#pragma unroll
                        for (int i = 0; i < 8; ++i) {
                            int t = __dp4a(a[i].x, b.x, accD[i * 8 + j]);
                            t = __dp4a(a[i].y, b.y, t);
                            t = __dp4a(a[i].z, b.z, t);
                            accD[i * 8 + j] = __dp4a(a[i].w, b.w, t);
                        }
                        if (j < 7) b = bn;
                    }
                }
                mbar_arrive(mbD + cs * 16 + 8);
                if (++cs == NST_D) { cs = 0; cp ^= 1; }
            }

            bar_sync(3, 512);   // Y
            bar_sync(3, 512);   // X: partials ready
            // combine (overlaps tensor's next-tile mainloop)
            const int* pbuf = (const int*)(smem + PART_OFF);
#pragma unroll
            for (int i = 0; i < 8; ++i) {
                int r = rowA0 + i;
                int* dst = g_C32 + (size_t)(m0 + r) * N_DIM + n0;
#pragma unroll
                for (int j = 0; j < 8; ++j) {
                    int v = pbuf[r * 128 + 16 * j + ng] + accD[i * 8 + j];
                    lmax = max(lmax, abs(v));
                    dst[16 * j + ng] = v;
                }
            }
        }

#pragma unroll
        for (int o = 16; o > 0; o >>= 1)
            lmax = max(lmax, __shfl_xor_sync(0xffffffffu, lmax, o));
        if (lane == 0) atomicMax(&s_bmax, lmax);
        bar_sync(2, 256);
        if (tid == 256) atomicMax(&g_max, s_bmax);
    }
}

// ----------------------------------------------------------------------------
__device__ __forceinline__ int compute_eff() {
    int m = g_max;
    if (m == 0) return 0;
    float mf = (float)m;
    unsigned bits = __float_as_uint(mf);
    int e  = (int)((bits >> 23) & 0xff) - 127;
    int bw = e + ((bits & 0x7fffffu) ? 1 : 0);
    int shift = bw - BITWIDTH;
    return shift > 1 ? shift : (shift == 1 ? 2 : 0);
}

__device__ __forceinline__ int psto_one(int x, int s) {
    int rt   = x >> s;
    int prob = x & ((1 << s) - 1);
    int h    = s >> 1;
    int qp   = prob >> h;
    int prn  = prob & ((1 << h) - 1);
    if (s & 1) prn <<= 1;
    int sgn = (x > 0) - (x < 0);
    int dec = (qp <= prn) ? 0 : sgn;
    int o = rt + dec;
    o = o > 127 ? 127 : (o < -127 ? -127 : o);
    return o;
}

__global__ void __launch_bounds__(256) epilogue_kernel(float* __restrict__ out) {
    const int eff = compute_eff();
    size_t i = (size_t)blockIdx.x * blockDim.x + threadIdx.x;
    int4 v = ((const int4*)g_C32)[i];
    float4 o;
    if (eff > 0) {
        o.x = (float)psto_one(v.x, eff);
        o.y = (float)psto_one(v.y, eff);
        o.z = (float)psto_one(v.z, eff);
        o.w = (float)psto_one(v.w, eff);
    } else {
        o.x = (float)(int8_t)(v.x);
        o.y = (float)(int8_t)(v.y);
        o.z = (float)(int8_t)(v.z);
        o.w = (float)(int8_t)(v.w);
    }
    ((float4*)out)[i] = o;
}

__global__ void tail_kernel(float* __restrict__ out, long long start, long long count,
                            const int* __restrict__ e1, const int* __restrict__ e2) {
    int eff = compute_eff();
    int8_t ev = (int8_t)(e1[0] + e2[0] + eff);
    for (long long i = threadIdx.x; i < count; i += blockDim.x)
        out[start + i] = (float)ev;
}

// ----------------------------------------------------------------------------
extern "C" void kernel_launch(void* const* d_in, const int* in_sizes, int n_in,
                              void* d_out, int out_size) {
    const int* act   = (const int*)d_in[0];
    const int* expin = (const int*)d_in[1];
    const int* wgt   = (const int*)d_in[2];
    const int* wexp  = (const int*)d_in[3];
    float* out = (float*)d_out;
    (void)in_sizes; (void)n_in;

    cudaFuncSetAttribute(gemm_persist_kernel,
                         cudaFuncAttributeMaxDynamicSharedMemorySize, SMEM_DYN);

    zero_max_kernel<<<1, 32>>>();
    pack_a_kernel<<<8192, 256>>>(act);
    pack_b_kernel<<<4096, 256>>>(wgt);

    gemm_persist_kernel<<<GRID_P, 512, SMEM_DYN>>>();

    long long total = (long long)M_DIM * N_DIM;
    epilogue_kernel<<<(int)(total / 4 / 256), 256>>>(out);
    long long tail = (long long)out_size - total;
    if (tail > 0) tail_kernel<<<1, 32>>>(out, total, tail, expin, wexp);
}

// round 10
// speedup vs baseline: 1.2757x; 1.1768x over previous
#include <cuda_runtime.h>
#include <cstdint>

// ============================================================================
// TiLinear hybrid v5 (persistent, fully decoupled groups):
//   warps 0-7 : mma.sync m16n8k32 IMMA, k-tiles [0,17)  (4-stage ring, +3 la)
//               -> partial to g_Ct
//   warps 8-15: dp4a (fma pipe, rt_SMSP=2), k-tiles [17,32) (3-stage, +2 la)
//               -> partial to g_Cd
// NO inter-group barriers after init. combine_kernel: Ct+Cd -> Ct, global max.
// epilogue: psto requantize g_Ct -> float out.
// Rates (validated R7-R9): IMMA 7.4k cyc/ktile, dp4a 8.2k cyc/ktile -> 17/15.
// ============================================================================

#define M_DIM 8192
#define N_DIM 4096
#define K_DIM 4096
#define BITWIDTH 7

#define NTILES_TOTAL 2048
#define GRID_P 148

#define KTILES 32
#define NKT_T 17
#define NKT_D (KTILES - NKT_T)   // 15
#define TILE_BYTES 16384
#define STAGE_BYTES 32768
#define NST_T 4
#define NST_D 3
#define TPOOL_OFF 0
#define DPOOL_OFF (NST_T * STAGE_BYTES)                  // 131072
#define CTRL_OFF  (DPOOL_OFF + NST_D * STAGE_BYTES)      // 229376
#define SMEM_DYN  (CTRL_OFF + 128)                       // 229504

__device__ __align__(128) int8_t g_A8[(size_t)M_DIM * K_DIM];   // 32 MB
__device__ __align__(128) int8_t g_B8[(size_t)N_DIM * K_DIM];   // 16 MB
__device__ __align__(16)  int    g_Ct[(size_t)M_DIM * N_DIM];   // 128 MB
__device__ __align__(16)  int    g_Cd[(size_t)M_DIM * N_DIM];   // 128 MB
__device__ int g_max;

// ----------------------------------------------------------------------------
__global__ void zero_max_kernel() {
    if (threadIdx.x == 0) g_max = 0;
}

__global__ void __launch_bounds__(256) pack_a_kernel(const int* __restrict__ src) {
    unsigned i = blockIdx.x * 256u + threadIdx.x;
    unsigned lc = i & 7u;
    unsigned m  = (i >> 3) & 8191u;
    unsigned kt = i >> 16;
    const int4* s = (const int4*)(src + (size_t)m * K_DIM + kt * 128 + lc * 16);
    uint32_t w[4];
#pragma unroll
    for (int j = 0; j < 4; ++j) {
        int4 v = s[j];
        w[j] = (uint32_t)(v.x & 0xff) | ((uint32_t)(v.y & 0xff) << 8) |
               ((uint32_t)(v.z & 0xff) << 16) | ((uint32_t)(v.w & 0xff) << 24);
    }
    unsigned lr = m & 127u;
    size_t base = (size_t)(kt * 64 + (m >> 7)) * TILE_BYTES;
    size_t off  = base + lr * 128 + (((lc ^ lr) & 7u) << 4);
    *(uint4*)(g_A8 + off) = make_uint4(w[0], w[1], w[2], w[3]);
}

__global__ void __launch_bounds__(256) pack_b_kernel(const int* __restrict__ src) {
    unsigned i = blockIdx.x * 256u + threadIdx.x;
    unsigned lc = i & 7u;
    unsigned n  = (i >> 3) & 4095u;
    unsigned kt = i >> 15;
    const int4* s = (const int4*)(src + (size_t)n * K_DIM + kt * 128 + lc * 16);
    uint32_t w[4];
#pragma unroll
    for (int j = 0; j < 4; ++j) {
        int4 v = s[j];
        w[j] = (uint32_t)(v.x & 0xff) | ((uint32_t)(v.y & 0xff) << 8) |
               ((uint32_t)(v.z & 0xff) << 16) | ((uint32_t)(v.w & 0xff) << 24);
    }
    unsigned lr = n & 127u;
    size_t base = (size_t)(kt * 32 + (n >> 7)) * TILE_BYTES;
    size_t off  = base + lr * 128 + (((lc ^ lr) & 7u) << 4);
    *(uint4*)(g_B8 + off) = make_uint4(w[0], w[1], w[2], w[3]);
}

// ----------------------------------------------------------------------------
__device__ __forceinline__ void mbar_init(uint32_t a, uint32_t cnt) {
    asm volatile("mbarrier.init.shared.b64 [%0], %1;" :: "r"(a), "r"(cnt) : "memory");
}
__device__ __forceinline__ void mbar_expect_tx(uint32_t a, uint32_t bytes) {
    asm volatile("mbarrier.arrive.expect_tx.shared.b64 _, [%0], %1;"
                 :: "r"(a), "r"(bytes) : "memory");
}
__device__ __forceinline__ void mbar_arrive(uint32_t a) {
    asm volatile("mbarrier.arrive.shared.b64 _, [%0];" :: "r"(a) : "memory");
}
__device__ __forceinline__ void mbar_wait(uint32_t a, uint32_t parity) {
    asm volatile(
        "{\n\t.reg .pred P;\n\t"
        "WAIT_%=:\n\t"
        "mbarrier.try_wait.parity.acquire.cta.shared::cta.b64 P, [%0], %1, 0x989680;\n\t"
        "@P bra.uni DONE_%=;\n\t"
        "bra.uni WAIT_%=;\n\t"
        "DONE_%=:\n\t}"
        :: "r"(a), "r"(parity) : "memory");
}
__device__ __forceinline__ void bulk_g2s(uint32_t dst, const void* src,
                                         uint32_t bytes, uint32_t mbar) {
    asm volatile(
        "cp.async.bulk.shared::cluster.global.mbarrier::complete_tx::bytes "
        "[%0], [%1], %2, [%3];"
        :: "r"(dst), "l"(src), "r"(bytes), "r"(mbar) : "memory");
}
__device__ __forceinline__ uint32_t swz_off(uint32_t row, uint32_t chunk) {
    return row * 128u + (((chunk ^ row) & 7u) << 4);
}
__device__ __forceinline__ void fill_blocks(uint32_t dst, uint32_t mbar,
                                            int ablk, int bblk) {
    mbar_expect_tx(mbar, STAGE_BYTES);
    bulk_g2s(dst, g_A8 + (size_t)ablk * TILE_BYTES, TILE_BYTES, mbar);
    bulk_g2s(dst + TILE_BYTES, g_B8 + (size_t)bblk * TILE_BYTES, TILE_BYTES, mbar);
}

// ----------------------------------------------------------------------------
__global__ void __launch_bounds__(512, 1) gemm_persist_kernel() {
    extern __shared__ __align__(1024) int8_t smem[];
    const int tid  = threadIdx.x;
    const int lane = tid & 31;
    const int warp = tid >> 5;
    const int bid  = blockIdx.x;
    const int ntiles = (NTILES_TOTAL - 1 - bid) / GRID_P + 1;
    const uint32_t sbase = (uint32_t)__cvta_generic_to_shared(smem);
    const uint32_t mbT = sbase + CTRL_OFF;          // 4 pairs (full, empty)
    const uint32_t mbD = sbase + CTRL_OFF + 64;     // 3 pairs

    if (tid == 0) {
#pragma unroll
        for (int s = 0; s < NST_T; ++s) {
            mbar_init(mbT + s * 16 + 0, 1);   // full (tx-based)
            mbar_init(mbT + s * 16 + 8, 8);   // empty: one arrive per warp
        }
#pragma unroll
        for (int s = 0; s < NST_D; ++s) {
            mbar_init(mbD + s * 16 + 0, 1);
            mbar_init(mbD + s * 16 + 8, 8);
        }
        asm volatile("fence.mbarrier_init.release.cluster;" ::: "memory");
    }
    __syncthreads();

    if (warp < 8) {
        // ==================== TENSOR GROUP (independent) ====================
        const int wm = warp >> 2, wn = warp & 3;
        const int total = ntiles * NKT_T;
        int cs = 0, cp = 0;        // consumer cursor
        int ps = 0, pp = 1;        // producer cursor

        auto t_fill = [&](int f) {
            int li = f / NKT_T;
            int kt = f - li * NKT_T;
            int tile = bid + li * GRID_P;
            mbar_wait(mbT + ps * 16 + 8, pp);
            fill_blocks(sbase + TPOOL_OFF + ps * STAGE_BYTES, mbT + ps * 16,
                        kt * 64 + (tile >> 5), kt * 32 + (tile & 31));
            if (++ps == NST_T) { ps = 0; pp ^= 1; }
        };

        if (tid == 0) {
            if (total > 0) t_fill(0);
            if (total > 1) t_fill(1);
            if (total > 2) t_fill(2);
        }

        for (int li = 0; li < ntiles; ++li) {
            const int tile = bid + li * GRID_P;
            const int m0 = (tile >> 5) * 128;
            const int n0 = (tile & 31) * 128;

            int acc[4][4][4];
#pragma unroll
            for (int a = 0; a < 4; ++a)
#pragma unroll
                for (int b = 0; b < 4; ++b)
#pragma unroll
                    for (int c = 0; c < 4; ++c) acc[a][b][c] = 0;

#pragma unroll 1
            for (int k = 0; k < NKT_T; ++k) {
                if (tid == 0) {
                    int f = li * NKT_T + k + 3;
                    if (f < total) t_fill(f);
                }
                mbar_wait(mbT + cs * 16, cp);

                const int8_t* sa = smem + TPOOL_OFF + cs * STAGE_BYTES;
                const int8_t* sb = sa + TILE_BYTES;
#pragma unroll
                for (int ks = 0; ks < 4; ++ks) {
                    uint32_t afr[4][4];
#pragma unroll
                    for (int mi = 0; mi < 4; ++mi) {
                        int r = wm * 64 + mi * 16 + (lane & 15);
                        int c = ks * 2 + (lane >> 4);
                        uint32_t addr =
                            (uint32_t)__cvta_generic_to_shared(sa + swz_off(r, c));
                        asm volatile(
                            "ldmatrix.sync.aligned.m8n8.x4.shared.b16 "
                            "{%0,%1,%2,%3}, [%4];\n"
                            : "=r"(afr[mi][0]), "=r"(afr[mi][1]),
                              "=r"(afr[mi][2]), "=r"(afr[mi][3])
                            : "r"(addr));
                    }
                    uint32_t bfr[4][2];
#pragma unroll
                    for (int ni = 0; ni < 4; ++ni) {
                        int r = wn * 32 + ni * 8 + (lane & 7);
                        int c = ks * 2 + ((lane >> 3) & 1);
                        uint32_t addr =
                            (uint32_t)__cvta_generic_to_shared(sb + swz_off(r, c));
                        asm volatile(
                            "ldmatrix.sync.aligned.m8n8.x2.shared.b16 {%0,%1}, [%2];\n"
                            : "=r"(bfr[ni][0]), "=r"(bfr[ni][1])
                            : "r"(addr));
                    }
#pragma unroll
                    for (int mi = 0; mi < 4; ++mi)
#pragma unroll
                        for (int ni = 0; ni < 4; ++ni) {
                            asm volatile(
                                "mma.sync.aligned.m16n8k32.row.col.s32.s8.s8.s32 "
                                "{%0,%1,%2,%3}, {%4,%5,%6,%7}, {%8,%9}, {%0,%1,%2,%3};\n"
                                : "+r"(acc[mi][ni][0]), "+r"(acc[mi][ni][1]),
                                  "+r"(acc[mi][ni][2]), "+r"(acc[mi][ni][3])
                                : "r"(afr[mi][0]), "r"(afr[mi][1]),
                                  "r"(afr[mi][2]), "r"(afr[mi][3]),
                                  "r"(bfr[ni][0]), "r"(bfr[ni][1]));
                        }
                }
                __syncwarp();
                if (lane == 0) mbar_arrive(mbT + cs * 16 + 8);
                if (++cs == NST_T) { cs = 0; cp ^= 1; }
            }

            // partial straight to global (no inter-group sync)
#pragma unroll
            for (int mi = 0; mi < 4; ++mi)
#pragma unroll
                for (int ni = 0; ni < 4; ++ni) {
                    int gm = m0 + wm * 64 + mi * 16 + (lane >> 2);
                    int gn = n0 + wn * 32 + ni * 8 + (lane & 3) * 2;
                    *(int2*)&g_Ct[(size_t)gm * N_DIM + gn] =
                        make_int2(acc[mi][ni][0], acc[mi][ni][1]);
                    *(int2*)&g_Ct[(size_t)(gm + 8) * N_DIM + gn] =
                        make_int2(acc[mi][ni][2], acc[mi][ni][3]);
                }
        }
    } else {
        // ==================== DP4A GROUP (independent) ====================
        const int wd = warp - 8;
        const int mg = lane >> 4;
        const int ng = lane & 15;
        const int rowA0 = 16 * wd + 8 * mg;
        const int total = ntiles * NKT_D;
        int cs = 0, cp = 0;
        int ps = 0, pp = 1;

        auto d_fill = [&](int f) {
            int li = f / NKT_D;
            int kd = f - li * NKT_D;
            int tile = bid + li * GRID_P;
            mbar_wait(mbD + ps * 16 + 8, pp);
            fill_blocks(sbase + DPOOL_OFF + ps * STAGE_BYTES, mbD + ps * 16,
                        (NKT_T + kd) * 64 + (tile >> 5),
                        (NKT_T + kd) * 32 + (tile & 31));
            if (++ps == NST_D) { ps = 0; pp ^= 1; }
        };

        if (tid == 256) {
            if (total > 0) d_fill(0);
            if (total > 1) d_fill(1);
        }

        for (int li = 0; li < ntiles; ++li) {
            const int tile = bid + li * GRID_P;
            const int m0 = (tile >> 5) * 128;
            const int n0 = (tile & 31) * 128;

            int accD[64];
#pragma unroll
            for (int j = 0; j < 64; ++j) accD[j] = 0;

#pragma unroll 1
            for (int k = 0; k < NKT_D; ++k) {
                if (tid == 256) {
                    int f = li * NKT_D + k + 2;
                    if (f < total) d_fill(f);
                }
                mbar_wait(mbD + cs * 16, cp);

                const int8_t* sa = smem + DPOOL_OFF + cs * STAGE_BYTES;
                const int8_t* sb = sa + TILE_BYTES;
#pragma unroll 1
                for (int cc = 0; cc < 8; ++cc) {
                    int4 a[8];
#pragma unroll
                    for (int i = 0; i < 8; ++i) {
                        int r = rowA0 + i;
                        a[i] = *(const int4*)(sa + r * 128 + (((cc ^ r) & 7) << 4));
                    }
                    const int boff = ((cc ^ ng) & 7) << 4;
                    int4 b = *(const int4*)(sb + ng * 128 + boff);
#pragma unroll
                    for (int j = 0; j < 8; ++j) {
                        int4 bn;
                        if (j < 7)
                            bn = *(const int4*)(sb + (16 * (j + 1) + ng) * 128 + boff);
#pragma unroll
                        for (int i = 0; i < 8; ++i) {
                            int t = __dp4a(a[i].x, b.x, accD[i * 8 + j]);
                            t = __dp4a(a[i].y, b.y, t);
                            t = __dp4a(a[i].z, b.z, t);
                            accD[i * 8 + j] = __dp4a(a[i].w, b.w, t);
                        }
                        if (j < 7) b = bn;
                    }
                }
                __syncwarp();
                if (lane == 0) mbar_arrive(mbD + cs * 16 + 8);
                if (++cs == NST_D) { cs = 0; cp ^= 1; }
            }

            // partial straight to global
#pragma unroll
            for (int i = 0; i < 8; ++i) {
                int* dst = g_Cd + (size_t)(m0 + rowA0 + i) * N_DIM + n0;
#pragma unroll
                for (int j = 0; j < 8; ++j)
                    dst[16 * j + ng] = accD[i * 8 + j];
            }
        }
    }
}

// ----------------------------------------------------------------------------
// combine: Ct += Cd (in place), global max reduce
__global__ void __launch_bounds__(256) combine_kernel() {
    __shared__ int s_bmax;
    if (threadIdx.x == 0) s_bmax = 0;
    __syncthreads();
    size_t i = (size_t)blockIdx.x * blockDim.x + threadIdx.x;
    int4 t = ((const int4*)g_Ct)[i];
    int4 d = ((const int4*)g_Cd)[i];
    int v0 = t.x + d.x, v1 = t.y + d.y, v2 = t.z + d.z, v3 = t.w + d.w;
    ((int4*)g_Ct)[i] = make_int4(v0, v1, v2, v3);
    int lmax = max(max(abs(v0), abs(v1)), max(abs(v2), abs(v3)));
#pragma unroll
    for (int o = 16; o > 0; o >>= 1)
        lmax = max(lmax, __shfl_xor_sync(0xffffffffu, lmax, o));
    if ((threadIdx.x & 31) == 0) atomicMax(&s_bmax, lmax);
    __syncthreads();
    if (threadIdx.x == 0) atomicMax(&g_max, s_bmax);
}

// ----------------------------------------------------------------------------
__device__ __forceinline__ int compute_eff() {
    int m = g_max;
    if (m == 0) return 0;
    float mf = (float)m;
    unsigned bits = __float_as_uint(mf);
    int e  = (int)((bits >> 23) & 0xff) - 127;
    int bw = e + ((bits & 0x7fffffu) ? 1 : 0);
    int shift = bw - BITWIDTH;
    return shift > 1 ? shift : (shift == 1 ? 2 : 0);
}

__device__ __forceinline__ int psto_one(int x, int s) {
    int rt   = x >> s;
    int prob = x & ((1 << s) - 1);
    int h    = s >> 1;
    int qp   = prob >> h;
    int prn  = prob & ((1 << h) - 1);
    if (s & 1) prn <<= 1;
    int sgn = (x > 0) - (x < 0);
    int dec = (qp <= prn) ? 0 : sgn;
    int o = rt + dec;
    o = o > 127 ? 127 : (o < -127 ? -127 : o);
    return o;
}

__global__ void __launch_bounds__(256) epilogue_kernel(float* __restrict__ out) {
    const int eff = compute_eff();
    size_t i = (size_t)blockIdx.x * blockDim.x + threadIdx.x;
    int4 v = ((const int4*)g_Ct)[i];
    float4 o;
    if (eff > 0) {
        o.x = (float)psto_one(v.x, eff);
        o.y = (float)psto_one(v.y, eff);
        o.z = (float)psto_one(v.z, eff);
        o.w = (float)psto_one(v.w, eff);
    } else {
        o.x = (float)(int8_t)(v.x);
        o.y = (float)(int8_t)(v.y);
        o.z = (float)(int8_t)(v.z);
        o.w = (float)(int8_t)(v.w);
    }
    ((float4*)out)[i] = o;
}

__global__ void tail_kernel(float* __restrict__ out, long long start, long long count,
                            const int* __restrict__ e1, const int* __restrict__ e2) {
    int eff = compute_eff();
    int8_t ev = (int8_t)(e1[0] + e2[0] + eff);
    for (long long i = threadIdx.x; i < count; i += blockDim.x)
        out[start + i] = (float)ev;
}

// ----------------------------------------------------------------------------
extern "C" void kernel_launch(void* const* d_in, const int* in_sizes, int n_in,
                              void* d_out, int out_size) {
    const int* act   = (const int*)d_in[0];
    const int* expin = (const int*)d_in[1];
    const int* wgt   = (const int*)d_in[2];
    const int* wexp  = (const int*)d_in[3];
    float* out = (float*)d_out;
    (void)in_sizes; (void)n_in;

    cudaFuncSetAttribute(gemm_persist_kernel,
                         cudaFuncAttributeMaxDynamicSharedMemorySize, SMEM_DYN);

    zero_max_kernel<<<1, 32>>>();
    pack_a_kernel<<<8192, 256>>>(act);
    pack_b_kernel<<<4096, 256>>>(wgt);

    gemm_persist_kernel<<<GRID_P, 512, SMEM_DYN>>>();

    long long total = (long long)M_DIM * N_DIM;           // 33554432
    combine_kernel<<<(int)(total / 4 / 256), 256>>>();     // 32768 blocks
    epilogue_kernel<<<(int)(total / 4 / 256), 256>>>(out);
    long long tail = (long long)out_size - total;
    if (tail > 0) tail_kernel<<<1, 32>>>(out, total, tail, expin, wexp);
}

// round 11
// speedup vs baseline: 1.2794x; 1.0029x over previous
#include <cuda_runtime.h>
#include <cstdint>

// ============================================================================
// TiLinear hybrid v6 (persistent, decoupled, arbiter-aware):
//   warps 0-7  : dp4a (fma pipe, HUGE issue count, low priority)  k [17,32)
//   warps 8-15 : mma.sync IMMA (few issues, latency-critical, HIGH priority
//                under the hi-wid-first arbiter)                  k [0,17)
// Tensor partial -> g_Ct, dp4a partial -> g_Cd. max_kernel computes the
// global max (read-only); epilogue adds Ct+Cd and requantizes.
// ============================================================================

#define M_DIM 8192
#define N_DIM 4096
#define K_DIM 4096
#define BITWIDTH 7

#define NTILES_TOTAL 2048
#define GRID_P 148

#define KTILES 32
#define NKT_T 17
#define NKT_D (KTILES - NKT_T)   // 15
#define TILE_BYTES 16384
#define STAGE_BYTES 32768
#define NST_T 4
#define NST_D 3
#define TPOOL_OFF 0
#define DPOOL_OFF (NST_T * STAGE_BYTES)                  // 131072
#define CTRL_OFF  (DPOOL_OFF + NST_D * STAGE_BYTES)      // 229376
#define SMEM_DYN  (CTRL_OFF + 128)                       // 229504

__device__ __align__(128) int8_t g_A8[(size_t)M_DIM * K_DIM];   // 32 MB
__device__ __align__(128) int8_t g_B8[(size_t)N_DIM * K_DIM];   // 16 MB
__device__ __align__(16)  int    g_Ct[(size_t)M_DIM * N_DIM];   // 128 MB
__device__ __align__(16)  int    g_Cd[(size_t)M_DIM * N_DIM];   // 128 MB
__device__ int g_max;

// ----------------------------------------------------------------------------
__global__ void zero_max_kernel() {
    if (threadIdx.x == 0) g_max = 0;
}

__global__ void __launch_bounds__(256) pack_a_kernel(const int* __restrict__ src) {
    unsigned i = blockIdx.x * 256u + threadIdx.x;
    unsigned lc = i & 7u;
    unsigned m  = (i >> 3) & 8191u;
    unsigned kt = i >> 16;
    const int4* s = (const int4*)(src + (size_t)m * K_DIM + kt * 128 + lc * 16);
    uint32_t w[4];
#pragma unroll
    for (int j = 0; j < 4; ++j) {
        int4 v = s[j];
        w[j] = (uint32_t)(v.x & 0xff) | ((uint32_t)(v.y & 0xff) << 8) |
               ((uint32_t)(v.z & 0xff) << 16) | ((uint32_t)(v.w & 0xff) << 24);
    }
    unsigned lr = m & 127u;
    size_t base = (size_t)(kt * 64 + (m >> 7)) * TILE_BYTES;
    size_t off  = base + lr * 128 + (((lc ^ lr) & 7u) << 4);
    *(uint4*)(g_A8 + off) = make_uint4(w[0], w[1], w[2], w[3]);
}

__global__ void __launch_bounds__(256) pack_b_kernel(const int* __restrict__ src) {
    unsigned i = blockIdx.x * 256u + threadIdx.x;
    unsigned lc = i & 7u;
    unsigned n  = (i >> 3) & 4095u;
    unsigned kt = i >> 15;
    const int4* s = (const int4*)(src + (size_t)n * K_DIM + kt * 128 + lc * 16);
    uint32_t w[4];
#pragma unroll
    for (int j = 0; j < 4; ++j) {
        int4 v = s[j];
        w[j] = (uint32_t)(v.x & 0xff) | ((uint32_t)(v.y & 0xff) << 8) |
               ((uint32_t)(v.z & 0xff) << 16) | ((uint32_t)(v.w & 0xff) << 24);
    }
    unsigned lr = n & 127u;
    size_t base = (size_t)(kt * 32 + (n >> 7)) * TILE_BYTES;
    size_t off  = base + lr * 128 + (((lc ^ lr) & 7u) << 4);
    *(uint4*)(g_B8 + off) = make_uint4(w[0], w[1], w[2], w[3]);
}

// ----------------------------------------------------------------------------
__device__ __forceinline__ void mbar_init(uint32_t a, uint32_t cnt) {
    asm volatile("mbarrier.init.shared.b64 [%0], %1;" :: "r"(a), "r"(cnt) : "memory");
}
__device__ __forceinline__ void mbar_expect_tx(uint32_t a, uint32_t bytes) {
    asm volatile("mbarrier.arrive.expect_tx.shared.b64 _, [%0], %1;"
                 :: "r"(a), "r"(bytes) : "memory");
}
__device__ __forceinline__ void mbar_arrive(uint32_t a) {
    asm volatile("mbarrier.arrive.shared.b64 _, [%0];" :: "r"(a) : "memory");
}
__device__ __forceinline__ void mbar_wait(uint32_t a, uint32_t parity) {
    asm volatile(
        "{\n\t.reg .pred P;\n\t"
        "WAIT_%=:\n\t"
        "mbarrier.try_wait.parity.acquire.cta.shared::cta.b64 P, [%0], %1, 0x989680;\n\t"
        "@P bra.uni DONE_%=;\n\t"
        "bra.uni WAIT_%=;\n\t"
        "DONE_%=:\n\t}"
        :: "r"(a), "r"(parity) : "memory");
}
__device__ __forceinline__ void bulk_g2s(uint32_t dst, const void* src,
                                         uint32_t bytes, uint32_t mbar) {
    asm volatile(
        "cp.async.bulk.shared::cluster.global.mbarrier::complete_tx::bytes "
        "[%0], [%1], %2, [%3];"
        :: "r"(dst), "l"(src), "r"(bytes), "r"(mbar) : "memory");
}
__device__ __forceinline__ uint32_t swz_off(uint32_t row, uint32_t chunk) {
    return row * 128u + (((chunk ^ row) & 7u) << 4);
}
__device__ __forceinline__ void fill_blocks(uint32_t dst, uint32_t mbar,
                                            int ablk, int bblk) {
    mbar_expect_tx(mbar, STAGE_BYTES);
    bulk_g2s(dst, g_A8 + (size_t)ablk * TILE_BYTES, TILE_BYTES, mbar);
    bulk_g2s(dst + TILE_BYTES, g_B8 + (size_t)bblk * TILE_BYTES, TILE_BYTES, mbar);
}

// ----------------------------------------------------------------------------
__global__ void __launch_bounds__(512, 1) gemm_persist_kernel() {
    extern __shared__ __align__(1024) int8_t smem[];
    const int tid  = threadIdx.x;
    const int lane = tid & 31;
    const int warp = tid >> 5;
    const int bid  = blockIdx.x;
    const int ntiles = (NTILES_TOTAL - 1 - bid) / GRID_P + 1;
    const uint32_t sbase = (uint32_t)__cvta_generic_to_shared(smem);
    const uint32_t mbT = sbase + CTRL_OFF;          // 4 pairs (full, empty)
    const uint32_t mbD = sbase + CTRL_OFF + 64;     // 3 pairs

    if (tid == 0) {
#pragma unroll
        for (int s = 0; s < NST_T; ++s) {
            mbar_init(mbT + s * 16 + 0, 1);   // full (tx-based)
            mbar_init(mbT + s * 16 + 8, 8);   // empty: one arrive per warp
        }
#pragma unroll
        for (int s = 0; s < NST_D; ++s) {
            mbar_init(mbD + s * 16 + 0, 1);
            mbar_init(mbD + s * 16 + 8, 8);
        }
        asm volatile("fence.mbarrier_init.release.cluster;" ::: "memory");
    }
    __syncthreads();

    if (warp >= 8) {
        // ============ TENSOR GROUP: warps 8-15 (HIGH arbiter priority) ============
        const int tw = warp - 8;
        const int wm = tw >> 2, wn = tw & 3;
        const int total = ntiles * NKT_T;
        int cs = 0, cp = 0;        // consumer cursor
        int ps = 0, pp = 1;        // producer cursor

        auto t_fill = [&](int f) {
            int li = f / NKT_T;
            int kt = f - li * NKT_T;
            int tile = bid + li * GRID_P;
            mbar_wait(mbT + ps * 16 + 8, pp);
            fill_blocks(sbase + TPOOL_OFF + ps * STAGE_BYTES, mbT + ps * 16,
                        kt * 64 + (tile >> 5), kt * 32 + (tile & 31));
            if (++ps == NST_T) { ps = 0; pp ^= 1; }
        };

        if (tid == 256) {
            if (total > 0) t_fill(0);
            if (total > 1) t_fill(1);
            if (total > 2) t_fill(2);
        }

        for (int li = 0; li < ntiles; ++li) {
            const int tile = bid + li * GRID_P;
            const int m0 = (tile >> 5) * 128;
            const int n0 = (tile & 31) * 128;

            int acc[4][4][4];
#pragma unroll
            for (int a = 0; a < 4; ++a)
#pragma unroll
                for (int b = 0; b < 4; ++b)
#pragma unroll
                    for (int c = 0; c < 4; ++c) acc[a][b][c] = 0;

#pragma unroll 1
            for (int k = 0; k < NKT_T; ++k) {
                if (tid == 256) {
                    int f = li * NKT_T + k + 3;
                    if (f < total) t_fill(f);
                }
                mbar_wait(mbT + cs * 16, cp);

                const int8_t* sa = smem + TPOOL_OFF + cs * STAGE_BYTES;
                const int8_t* sb = sa + TILE_BYTES;
#pragma unroll
                for (int ks = 0; ks < 4; ++ks) {
                    uint32_t afr[4][4];
#pragma unroll
                    for (int mi = 0; mi < 4; ++mi) {
                        int r = wm * 64 + mi * 16 + (lane & 15);
                        int c = ks * 2 + (lane >> 4);
                        uint32_t addr =
                            (uint32_t)__cvta_generic_to_shared(sa + swz_off(r, c));
                        asm volatile(
                            "ldmatrix.sync.aligned.m8n8.x4.shared.b16 "
                            "{%0,%1,%2,%3}, [%4];\n"
                            : "=r"(afr[mi][0]), "=r"(afr[mi][1]),
                              "=r"(afr[mi][2]), "=r"(afr[mi][3])
                            : "r"(addr));
                    }
                    uint32_t bfr[4][2];
#pragma unroll
                    for (int ni = 0; ni < 4; ++ni) {
                        int r = wn * 32 + ni * 8 + (lane & 7);
                        int c = ks * 2 + ((lane >> 3) & 1);
                        uint32_t addr =
                            (uint32_t)__cvta_generic_to_shared(sb + swz_off(r, c));
                        asm volatile(
                            "ldmatrix.sync.aligned.m8n8.x2.shared.b16 {%0,%1}, [%2];\n"
                            : "=r"(bfr[ni][0]), "=r"(bfr[ni][1])
                            : "r"(addr));
                    }
#pragma unroll
                    for (int mi = 0; mi < 4; ++mi)
#pragma unroll
                        for (int ni = 0; ni < 4; ++ni) {
                            asm volatile(
                                "mma.sync.aligned.m16n8k32.row.col.s32.s8.s8.s32 "
                                "{%0,%1,%2,%3}, {%4,%5,%6,%7}, {%8,%9}, {%0,%1,%2,%3};\n"
                                : "+r"(acc[mi][ni][0]), "+r"(acc[mi][ni][1]),
                                  "+r"(acc[mi][ni][2]), "+r"(acc[mi][ni][3])
                                : "r"(afr[mi][0]), "r"(afr[mi][1]),
                                  "r"(afr[mi][2]), "r"(afr[mi][3]),
                                  "r"(bfr[ni][0]), "r"(bfr[ni][1]));
                        }
                }
                __syncwarp();
                if (lane == 0) mbar_arrive(mbT + cs * 16 + 8);
                if (++cs == NST_T) { cs = 0; cp ^= 1; }
            }

            // partial straight to global (no inter-group sync)
#pragma unroll
            for (int mi = 0; mi < 4; ++mi)
#pragma unroll
                for (int ni = 0; ni < 4; ++ni) {
                    int gm = m0 + wm * 64 + mi * 16 + (lane >> 2);
                    int gn = n0 + wn * 32 + ni * 8 + (lane & 3) * 2;
                    *(int2*)&g_Ct[(size_t)gm * N_DIM + gn] =
                        make_int2(acc[mi][ni][0], acc[mi][ni][1]);
                    *(int2*)&g_Ct[(size_t)(gm + 8) * N_DIM + gn] =
                        make_int2(acc[mi][ni][2], acc[mi][ni][3]);
                }
        }
    } else {
        // ============ DP4A GROUP: warps 0-7 (low priority; has slack) ============
        const int wd = warp;
        const int mg = lane >> 4;
        const int ng = lane & 15;
        const int rowA0 = 16 * wd + 8 * mg;
        const int total = ntiles * NKT_D;
        int cs = 0, cp = 0;
        int ps = 0, pp = 1;

        auto d_fill = [&](int f) {
            int li = f / NKT_D;
            int kd = f - li * NKT_D;
            int tile = bid + li * GRID_P;
            mbar_wait(mbD + ps * 16 + 8, pp);
            fill_blocks(sbase + DPOOL_OFF + ps * STAGE_BYTES, mbD + ps * 16,
                        (NKT_T + kd) * 64 + (tile >> 5),
                        (NKT_T + kd) * 32 + (tile & 31));
            if (++ps == NST_D) { ps = 0; pp ^= 1; }
        };

        if (tid == 0) {
            if (total > 0) d_fill(0);
            if (total > 1) d_fill(1);
        }

        for (int li = 0; li < ntiles; ++li) {
            const int tile = bid + li * GRID_P;
            const int m0 = (tile >> 5) * 128;
            const int n0 = (tile & 31) * 128;

            int accD[64];
#pragma unroll
            for (int j = 0; j < 64; ++j) accD[j] = 0;

#pragma unroll 1
            for (int k = 0; k < NKT_D; ++k) {
                if (tid == 0) {
                    int f = li * NKT_D + k + 2;
                    if (f < total) d_fill(f);
                }
                mbar_wait(mbD + cs * 16, cp);

                const int8_t* sa = smem + DPOOL_OFF + cs * STAGE_BYTES;
                const int8_t* sb = sa + TILE_BYTES;
#pragma unroll 1
                for (int cc = 0; cc < 8; ++cc) {
                    int4 a[8];
#pragma unroll
                    for (int i = 0; i < 8; ++i) {
                        int r = rowA0 + i;
                        a[i] = *(const int4*)(sa + r * 128 + (((cc ^ r) & 7) << 4));
                    }
                    const int boff = ((cc ^ ng) & 7) << 4;
                    int4 b = *(const int4*)(sb + ng * 128 + boff);
#pragma unroll
                    for (int j = 0; j < 8; ++j) {
                        int4 bn;
                        if (j < 7)
                            bn = *(const int4*)(sb + (16 * (j + 1) + ng) * 128 + boff);
#pragma unroll
                        for (int i = 0; i < 8; ++i) {
                            int t = __dp4a(a[i].x, b.x, accD[i * 8 + j]);
                            t = __dp4a(a[i].y, b.y, t);
                            t = __dp4a(a[i].z, b.z, t);
                            accD[i * 8 + j] = __dp4a(a[i].w, b.w, t);
                        }
                        if (j < 7) b = bn;
                    }
                }
                __syncwarp();
                if (lane == 0) mbar_arrive(mbD + cs * 16 + 8);
                if (++cs == NST_D) { cs = 0; cp ^= 1; }
            }

            // partial straight to global
#pragma unroll
            for (int i = 0; i < 8; ++i) {
                int* dst = g_Cd + (size_t)(m0 + rowA0 + i) * N_DIM + n0;
#pragma unroll
                for (int j = 0; j < 8; ++j)
                    dst[16 * j + ng] = accD[i * 8 + j];
            }
        }
    }
}

// ----------------------------------------------------------------------------
// max-only pass: no store of the sum (epilogue recomputes it)
__global__ void __launch_bounds__(256) max_kernel() {
    __shared__ int s_bmax;
    if (threadIdx.x == 0) s_bmax = 0;
    __syncthreads();
    size_t i = (size_t)blockIdx.x * blockDim.x + threadIdx.x;
    int4 t = ((const int4*)g_Ct)[i];
    int4 d = ((const int4*)g_Cd)[i];
    int v0 = t.x + d.x, v1 = t.y + d.y, v2 = t.z + d.z, v3 = t.w + d.w;
    int lmax = max(max(abs(v0), abs(v1)), max(abs(v2), abs(v3)));
#pragma unroll
    for (int o = 16; o > 0; o >>= 1)
        lmax = max(lmax, __shfl_xor_sync(0xffffffffu, lmax, o));
    if ((threadIdx.x & 31) == 0) atomicMax(&s_bmax, lmax);
    __syncthreads();
    if (threadIdx.x == 0) atomicMax(&g_max, s_bmax);
}

// ----------------------------------------------------------------------------
__device__ __forceinline__ int compute_eff() {
    int m = g_max;
    if (m == 0) return 0;
    float mf = (float)m;
    unsigned bits = __float_as_uint(mf);
    int e  = (int)((bits >> 23) & 0xff) - 127;
    int bw = e + ((bits & 0x7fffffu) ? 1 : 0);
    int shift = bw - BITWIDTH;
    return shift > 1 ? shift : (shift == 1 ? 2 : 0);
}

__device__ __forceinline__ int psto_one(int x, int s) {
    int rt   = x >> s;
    int prob = x & ((1 << s) - 1);
    int h    = s >> 1;
    int qp   = prob >> h;
    int prn  = prob & ((1 << h) - 1);
    if (s & 1) prn <<= 1;
    int sgn = (x > 0) - (x < 0);
    int dec = (qp <= prn) ? 0 : sgn;
    int o = rt + dec;
    o = o > 127 ? 127 : (o < -127 ? -127 : o);
    return o;
}

__global__ void __launch_bounds__(256) epilogue_kernel(float* __restrict__ out) {
    const int eff = compute_eff();
    size_t i = (size_t)blockIdx.x * blockDim.x + threadIdx.x;
    int4 t = ((const int4*)g_Ct)[i];
    int4 d = ((const int4*)g_Cd)[i];
    int v0 = t.x + d.x, v1 = t.y + d.y, v2 = t.z + d.z, v3 = t.w + d.w;
    float4 o;
    if (eff > 0) {
        o.x = (float)psto_one(v0, eff);
        o.y = (float)psto_one(v1, eff);
        o.z = (float)psto_one(v2, eff);
        o.w = (float)psto_one(v3, eff);
    } else {
        o.x = (float)(int8_t)(v0);
        o.y = (float)(int8_t)(v1);
        o.z = (float)(int8_t)(v2);
        o.w = (float)(int8_t)(v3);
    }
    ((float4*)out)[i] = o;
}

__global__ void tail_kernel(float* __restrict__ out, long long start, long long count,
                            const int* __restrict__ e1, const int* __restrict__ e2) {
    int eff = compute_eff();
    int8_t ev = (int8_t)(e1[0] + e2[0] + eff);
    for (long long i = threadIdx.x; i < count; i += blockDim.x)
        out[start + i] = (float)ev;
}

// ----------------------------------------------------------------------------
extern "C" void kernel_launch(void* const* d_in, const int* in_sizes, int n_in,
                              void* d_out, int out_size) {
    const int* act   = (const int*)d_in[0];
    const int* expin = (const int*)d_in[1];
    const int* wgt   = (const int*)d_in[2];
    const int* wexp  = (const int*)d_in[3];
    float* out = (float*)d_out;
    (void)in_sizes; (void)n_in;

    cudaFuncSetAttribute(gemm_persist_kernel,
                         cudaFuncAttributeMaxDynamicSharedMemorySize, SMEM_DYN);

    zero_max_kernel<<<1, 32>>>();
    pack_a_kernel<<<8192, 256>>>(act);
    pack_b_kernel<<<4096, 256>>>(wgt);

    gemm_persist_kernel<<<GRID_P, 512, SMEM_DYN>>>();

    long long total = (long long)M_DIM * N_DIM;           // 33554432
    max_kernel<<<(int)(total / 4 / 256), 256>>>();         // 32768 blocks
    epilogue_kernel<<<(int)(total / 4 / 256), 256>>>(out);
    long long tail = (long long)out_size - total;
    if (tail > 0) tail_kernel<<<1, 32>>>(out, total, tail, expin, wexp);
}

// round 12
// speedup vs baseline: 1.3004x; 1.0164x over previous
#include <cuda_runtime.h>
#include <cstdint>

// ============================================================================
// TiLinear hybrid v7 (persistent, in-kernel combine + max):
//   warps 0-7  : dp4a (fma pipe), k-tiles [17,32), 2-stage ring, +1 la
//                -> partial into smem pbuf (pfull/pfree handshake)
//   warps 8-15 : mma.sync IMMA,  k-tiles [0,17),  3-stage ring, +2 la
//                -> adds pbuf, computes |max|, stores combined C to g_C
// No max_kernel; epilogue reads the single combined buffer.
// ============================================================================

#define M_DIM 8192
#define N_DIM 4096
#define K_DIM 4096
#define BITWIDTH 7

#define NTILES_TOTAL 2048
#define GRID_P 148

#define KTILES 32
#define NKT_T 17
#define NKT_D (KTILES - NKT_T)   // 15
#define TILE_BYTES 16384
#define STAGE_BYTES 32768
#define NST_T 3
#define NST_D 2
#define PB_STRIDE 132            // ints; 132%32=4 -> conflict-free column reads
#define TPOOL_OFF 0
#define DPOOL_OFF (NST_T * STAGE_BYTES)                  // 98304
#define PART_OFF  (DPOOL_OFF + NST_D * STAGE_BYTES)      // 163840
#define PART_BYTES (128 * PB_STRIDE * 4)                 // 67584
#define CTRL_OFF  (PART_OFF + PART_BYTES)                // 231424
#define SMEM_DYN  (CTRL_OFF + 128)                       // 231552 (< 232448)

__device__ __align__(128) int8_t g_A8[(size_t)M_DIM * K_DIM];   // 32 MB
__device__ __align__(128) int8_t g_B8[(size_t)N_DIM * K_DIM];   // 16 MB
__device__ __align__(16)  int    g_C[(size_t)M_DIM * N_DIM];    // 128 MB
__device__ int g_max;

// ----------------------------------------------------------------------------
__global__ void zero_max_kernel() {
    if (threadIdx.x == 0) g_max = 0;
}

__global__ void __launch_bounds__(256) pack_a_kernel(const int* __restrict__ src) {
    unsigned i = blockIdx.x * 256u + threadIdx.x;
    unsigned lc = i & 7u;
    unsigned m  = (i >> 3) & 8191u;
    unsigned kt = i >> 16;
    const int4* s = (const int4*)(src + (size_t)m * K_DIM + kt * 128 + lc * 16);
    uint32_t w[4];
#pragma unroll
    for (int j = 0; j < 4; ++j) {
        int4 v = s[j];
        w[j] = (uint32_t)(v.x & 0xff) | ((uint32_t)(v.y & 0xff) << 8) |
               ((uint32_t)(v.z & 0xff) << 16) | ((uint32_t)(v.w & 0xff) << 24);
    }
    unsigned lr = m & 127u;
    size_t base = (size_t)(kt * 64 + (m >> 7)) * TILE_BYTES;
    size_t off  = base + lr * 128 + (((lc ^ lr) & 7u) << 4);
    *(uint4*)(g_A8 + off) = make_uint4(w[0], w[1], w[2], w[3]);
}

__global__ void __launch_bounds__(256) pack_b_kernel(const int* __restrict__ src) {
    unsigned i = blockIdx.x * 256u + threadIdx.x;
    unsigned lc = i & 7u;
    unsigned n  = (i >> 3) & 4095u;
    unsigned kt = i >> 15;
    const int4* s = (const int4*)(src + (size_t)n * K_DIM + kt * 128 + lc * 16);
    uint32_t w[4];
#pragma unroll
    for (int j = 0; j < 4; ++j) {
        int4 v = s[j];
        w[j] = (uint32_t)(v.x & 0xff) | ((uint32_t)(v.y & 0xff) << 8) |
               ((uint32_t)(v.z & 0xff) << 16) | ((uint32_t)(v.w & 0xff) << 24);
    }
    unsigned lr = n & 127u;
    size_t base = (size_t)(kt * 32 + (n >> 7)) * TILE_BYTES;
    size_t off  = base + lr * 128 + (((lc ^ lr) & 7u) << 4);
    *(uint4*)(g_B8 + off) = make_uint4(w[0], w[1], w[2], w[3]);
}

// ----------------------------------------------------------------------------
__device__ __forceinline__ void mbar_init(uint32_t a, uint32_t cnt) {
    asm volatile("mbarrier.init.shared.b64 [%0], %1;" :: "r"(a), "r"(cnt) : "memory");
}
__device__ __forceinline__ void mbar_expect_tx(uint32_t a, uint32_t bytes) {
    asm volatile("mbarrier.arrive.expect_tx.shared.b64 _, [%0], %1;"
                 :: "r"(a), "r"(bytes) : "memory");
}
__device__ __forceinline__ void mbar_arrive(uint32_t a) {
    asm volatile("mbarrier.arrive.shared.b64 _, [%0];" :: "r"(a) : "memory");
}
__device__ __forceinline__ void mbar_wait(uint32_t a, uint32_t parity) {
    asm volatile(
        "{\n\t.reg .pred P;\n\t"
        "WAIT_%=:\n\t"
        "mbarrier.try_wait.parity.acquire.cta.shared::cta.b64 P, [%0], %1, 0x989680;\n\t"
        "@P bra.uni DONE_%=;\n\t"
        "bra.uni WAIT_%=;\n\t"
        "DONE_%=:\n\t}"
        :: "r"(a), "r"(parity) : "memory");
}
__device__ __forceinline__ void bulk_g2s(uint32_t dst, const void* src,
                                         uint32_t bytes, uint32_t mbar) {
    asm volatile(
        "cp.async.bulk.shared::cluster.global.mbarrier::complete_tx::bytes "
        "[%0], [%1], %2, [%3];"
        :: "r"(dst), "l"(src), "r"(bytes), "r"(mbar) : "memory");
}
__device__ __forceinline__ uint32_t swz_off(uint32_t row, uint32_t chunk) {
    return row * 128u + (((chunk ^ row) & 7u) << 4);
}
__device__ __forceinline__ void fill_blocks(uint32_t dst, uint32_t mbar,
                                            int ablk, int bblk) {
    mbar_expect_tx(mbar, STAGE_BYTES);
    bulk_g2s(dst, g_A8 + (size_t)ablk * TILE_BYTES, TILE_BYTES, mbar);
    bulk_g2s(dst + TILE_BYTES, g_B8 + (size_t)bblk * TILE_BYTES, TILE_BYTES, mbar);
}

// ----------------------------------------------------------------------------
__global__ void __launch_bounds__(512, 1) gemm_persist_kernel() {
    extern __shared__ __align__(1024) int8_t smem[];
    const int tid  = threadIdx.x;
    const int lane = tid & 31;
    const int warp = tid >> 5;
    const int bid  = blockIdx.x;
    const int ntiles = (NTILES_TOTAL - 1 - bid) / GRID_P + 1;
    const uint32_t sbase = (uint32_t)__cvta_generic_to_shared(smem);
    const uint32_t mbT   = sbase + CTRL_OFF;        // 3 pairs
    const uint32_t mbD   = sbase + CTRL_OFF + 48;   // 2 pairs
    const uint32_t pfull = sbase + CTRL_OFF + 80;   // dp4a -> tensor
    const uint32_t pfree = sbase + CTRL_OFF + 88;   // tensor -> dp4a
    int* pbuf = (int*)(smem + PART_OFF);

    if (tid == 0) {
#pragma unroll
        for (int s = 0; s < NST_T; ++s) {
            mbar_init(mbT + s * 16 + 0, 1);   // full (tx)
            mbar_init(mbT + s * 16 + 8, 8);   // empty (one arrive per warp)
        }
#pragma unroll
        for (int s = 0; s < NST_D; ++s) {
            mbar_init(mbD + s * 16 + 0, 1);
            mbar_init(mbD + s * 16 + 8, 8);
        }
        mbar_init(pfull, 8);
        mbar_init(pfree, 8);
        asm volatile("fence.mbarrier_init.release.cluster;" ::: "memory");
    }
    __syncthreads();

    if (warp >= 8) {
        // ================= TENSOR GROUP: warps 8-15, k [0,17) =================
        const int tw = warp - 8;
        const int wm = tw >> 2, wn = tw & 3;
        const int total = ntiles * NKT_T;
        int cs = 0, cp = 0;
        int ps = 0, pp = 1;
        int pt = 0;            // pfull wait parity
        int lmax = 0;

        auto t_fill = [&](int f) {
            int li = f / NKT_T;
            int kt = f - li * NKT_T;
            int tile = bid + li * GRID_P;
            mbar_wait(mbT + ps * 16 + 8, pp);
            fill_blocks(sbase + TPOOL_OFF + ps * STAGE_BYTES, mbT + ps * 16,
                        kt * 64 + (tile >> 5), kt * 32 + (tile & 31));
            if (++ps == NST_T) { ps = 0; pp ^= 1; }
        };

        if (tid == 256) {
            if (total > 0) t_fill(0);
            if (total > 1) t_fill(1);
        }

        for (int li = 0; li < ntiles; ++li) {
            const int tile = bid + li * GRID_P;
            const int m0 = (tile >> 5) * 128;
            const int n0 = (tile & 31) * 128;

            int acc[4][4][4];
#pragma unroll
            for (int a = 0; a < 4; ++a)
#pragma unroll
                for (int b = 0; b < 4; ++b)
#pragma unroll
                    for (int c = 0; c < 4; ++c) acc[a][b][c] = 0;

#pragma unroll 1
            for (int k = 0; k < NKT_T; ++k) {
                if (tid == 256) {
                    int f = li * NKT_T + k + 2;
                    if (f < total) t_fill(f);
                }
                mbar_wait(mbT + cs * 16, cp);

                const int8_t* sa = smem + TPOOL_OFF + cs * STAGE_BYTES;
                const int8_t* sb = sa + TILE_BYTES;
#pragma unroll
                for (int ks = 0; ks < 4; ++ks) {
                    uint32_t afr[4][4];
#pragma unroll
                    for (int mi = 0; mi < 4; ++mi) {
                        int r = wm * 64 + mi * 16 + (lane & 15);
                        int c = ks * 2 + (lane >> 4);
                        uint32_t addr =
                            (uint32_t)__cvta_generic_to_shared(sa + swz_off(r, c));
                        asm volatile(
                            "ldmatrix.sync.aligned.m8n8.x4.shared.b16 "
                            "{%0,%1,%2,%3}, [%4];\n"
                            : "=r"(afr[mi][0]), "=r"(afr[mi][1]),
                              "=r"(afr[mi][2]), "=r"(afr[mi][3])
                            : "r"(addr));
                    }
                    uint32_t bfr[4][2];
#pragma unroll
                    for (int ni = 0; ni < 4; ++ni) {
                        int r = wn * 32 + ni * 8 + (lane & 7);
                        int c = ks * 2 + ((lane >> 3) & 1);
                        uint32_t addr =
                            (uint32_t)__cvta_generic_to_shared(sb + swz_off(r, c));
                        asm volatile(
                            "ldmatrix.sync.aligned.m8n8.x2.shared.b16 {%0,%1}, [%2];\n"
                            : "=r"(bfr[ni][0]), "=r"(bfr[ni][1])
                            : "r"(addr));
                    }
#pragma unroll
                    for (int mi = 0; mi < 4; ++mi)
#pragma unroll
                        for (int ni = 0; ni < 4; ++ni) {
                            asm volatile(
                                "mma.sync.aligned.m16n8k32.row.col.s32.s8.s8.s32 "
                                "{%0,%1,%2,%3}, {%4,%5,%6,%7}, {%8,%9}, {%0,%1,%2,%3};\n"
                                : "+r"(acc[mi][ni][0]), "+r"(acc[mi][ni][1]),
                                  "+r"(acc[mi][ni][2]), "+r"(acc[mi][ni][3])
                                : "r"(afr[mi][0]), "r"(afr[mi][1]),
                                  "r"(afr[mi][2]), "r"(afr[mi][3]),
                                  "r"(bfr[ni][0]), "r"(bfr[ni][1]));
                        }
                }
                __syncwarp();
                if (lane == 0) mbar_arrive(mbT + cs * 16 + 8);
                if (++cs == NST_T) { cs = 0; cp ^= 1; }
            }

            // wait for dp4a partial, combine, max, store
            mbar_wait(pfull, pt);
            pt ^= 1;
#pragma unroll
            for (int mi = 0; mi < 4; ++mi)
#pragma unroll
                for (int ni = 0; ni < 4; ++ni) {
                    int r  = wm * 64 + mi * 16 + (lane >> 2);
                    int c  = wn * 32 + ni * 8 + (lane & 3) * 2;
                    int2 p0 = *(int2*)&pbuf[r * PB_STRIDE + c];
                    int2 p1 = *(int2*)&pbuf[(r + 8) * PB_STRIDE + c];
                    int v0 = acc[mi][ni][0] + p0.x;
                    int v1 = acc[mi][ni][1] + p0.y;
                    int v2 = acc[mi][ni][2] + p1.x;
                    int v3 = acc[mi][ni][3] + p1.y;
                    lmax = max(lmax, abs(v0)); lmax = max(lmax, abs(v1));
                    lmax = max(lmax, abs(v2)); lmax = max(lmax, abs(v3));
                    int gm = m0 + r, gn = n0 + c;
                    *(int2*)&g_C[(size_t)gm * N_DIM + gn]       = make_int2(v0, v1);
                    *(int2*)&g_C[(size_t)(gm + 8) * N_DIM + gn] = make_int2(v2, v3);
                }
            __syncwarp();
            if (lane == 0) mbar_arrive(pfree);
        }

#pragma unroll
        for (int o = 16; o > 0; o >>= 1)
            lmax = max(lmax, __shfl_xor_sync(0xffffffffu, lmax, o));
        if (lane == 0) atomicMax(&g_max, lmax);
    } else {
        // ================= DP4A GROUP: warps 0-7, k [17,32) =================
        const int wd = warp;
        const int mg = lane >> 4;
        const int ng = lane & 15;
        const int rowA0 = 16 * wd + 8 * mg;
        const int total = ntiles * NKT_D;
        int cs = 0, cp = 0;
        int ps = 0, pp = 1;
        int pd = 1;            // pfree wait parity (fresh barrier passes at 1)

        auto d_fill = [&](int f) {
            int li = f / NKT_D;
            int kd = f - li * NKT_D;
            int tile = bid + li * GRID_P;
            mbar_wait(mbD + ps * 16 + 8, pp);
            fill_blocks(sbase + DPOOL_OFF + ps * STAGE_BYTES, mbD + ps * 16,
                        (NKT_T + kd) * 64 + (tile >> 5),
                        (NKT_T + kd) * 32 + (tile & 31));
            if (++ps == NST_D) { ps = 0; pp ^= 1; }
        };

        if (tid == 0 && total > 0) d_fill(0);

        for (int li = 0; li < ntiles; ++li) {
            int accD[64];
#pragma unroll
            for (int j = 0; j < 64; ++j) accD[j] = 0;

#pragma unroll 1
            for (int k = 0; k < NKT_D; ++k) {
                if (tid == 0) {
                    int f = li * NKT_D + k + 1;   // +1 lookahead (2-stage ring)
                    if (f < total) d_fill(f);
                }
                mbar_wait(mbD + cs * 16, cp);

                const int8_t* sa = smem + DPOOL_OFF + cs * STAGE_BYTES;
                const int8_t* sb = sa + TILE_BYTES;
#pragma unroll 1
                for (int cc = 0; cc < 8; ++cc) {
                    int4 a[8];
#pragma unroll
                    for (int i = 0; i < 8; ++i) {
                        int r = rowA0 + i;
                        a[i] = *(const int4*)(sa + r * 128 + (((cc ^ r) & 7) << 4));
                    }
                    const int boff = ((cc ^ ng) & 7) << 4;
                    int4 b = *(const int4*)(sb + ng * 128 + boff);
#pragma unroll
                    for (int j = 0; j < 8; ++j) {
                        int4 bn;
                        if (j < 7)
                            bn = *(const int4*)(sb + (16 * (j + 1) + ng) * 128 + boff);
#pragma unroll
                        for (int i = 0; i < 8; ++i) {
                            int t = __dp4a(a[i].x, b.x, accD[i * 8 + j]);
                            t = __dp4a(a[i].y, b.y, t);
                            t = __dp4a(a[i].z, b.z, t);
                            accD[i * 8 + j] = __dp4a(a[i].w, b.w, t);
                        }
                        if (j < 7) b = bn;
                    }
                }
                __syncwarp();
                if (lane == 0) mbar_arrive(mbD + cs * 16 + 8);
                if (++cs == NST_D) { cs = 0; cp ^= 1; }
            }

            // hand the partial to the tensor group through smem
            mbar_wait(pfree, pd);
            pd ^= 1;
#pragma unroll
            for (int i = 0; i < 8; ++i) {
                int* row = pbuf + (rowA0 + i) * PB_STRIDE;
#pragma unroll
                for (int j = 0; j < 8; ++j)
                    row[16 * j + ng] = accD[i * 8 + j];
            }
            __syncwarp();
            if (lane == 0) mbar_arrive(pfull);
        }
    }
}

// ----------------------------------------------------------------------------
__device__ __forceinline__ int compute_eff() {
    int m = g_max;
    if (m == 0) return 0;
    float mf = (float)m;
    unsigned bits = __float_as_uint(mf);
    int e  = (int)((bits >> 23) & 0xff) - 127;
    int bw = e + ((bits & 0x7fffffu) ? 1 : 0);
    int shift = bw - BITWIDTH;
    return shift > 1 ? shift : (shift == 1 ? 2 : 0);
}

__device__ __forceinline__ int psto_one(int x, int s) {
    int rt   = x >> s;
    int prob = x & ((1 << s) - 1);
    int h    = s >> 1;
    int qp   = prob >> h;
    int prn  = prob & ((1 << h) - 1);
    if (s & 1) prn <<= 1;
    int sgn = (x > 0) - (x < 0);
    int dec = (qp <= prn) ? 0 : sgn;
    int o = rt + dec;
    o = o > 127 ? 127 : (o < -127 ? -127 : o);
    return o;
}

__global__ void __launch_bounds__(256) epilogue_kernel(float* __restrict__ out) {
    const int eff = compute_eff();
    size_t i = (size_t)blockIdx.x * blockDim.x + threadIdx.x;
    int4 v = ((const int4*)g_C)[i];
    float4 o;
    if (eff > 0) {
        o.x = (float)psto_one(v.x, eff);
        o.y = (float)psto_one(v.y, eff);
        o.z = (float)psto_one(v.z, eff);
        o.w = (float)psto_one(v.w, eff);
    } else {
        o.x = (float)(int8_t)(v.x);
        o.y = (float)(int8_t)(v.y);
        o.z = (float)(int8_t)(v.z);
        o.w = (float)(int8_t)(v.w);
    }
    ((float4*)out)[i] = o;
}

__global__ void tail_kernel(float* __restrict__ out, long long start, long long count,
                            const int* __restrict__ e1, const int* __restrict__ e2) {
    int eff = compute_eff();
    int8_t ev = (int8_t)(e1[0] + e2[0] + eff);
    for (long long i = threadIdx.x; i < count; i += blockDim.x)
        out[start + i] = (float)ev;
}

// ----------------------------------------------------------------------------
extern "C" void kernel_launch(void* const* d_in, const int* in_sizes, int n_in,
                              void* d_out, int out_size) {
    const int* act   = (const int*)d_in[0];
    const int* expin = (const int*)d_in[1];
    const int* wgt   = (const int*)d_in[2];
    const int* wexp  = (const int*)d_in[3];
    float* out = (float*)d_out;
    (void)in_sizes; (void)n_in;

    cudaFuncSetAttribute(gemm_persist_kernel,
                         cudaFuncAttributeMaxDynamicSharedMemorySize, SMEM_DYN);

    zero_max_kernel<<<1, 32>>>();
    pack_a_kernel<<<8192, 256>>>(act);
    pack_b_kernel<<<4096, 256>>>(wgt);

    gemm_persist_kernel<<<GRID_P, 512, SMEM_DYN>>>();

    long long total = (long long)M_DIM * N_DIM;           // 33554432
    epilogue_kernel<<<(int)(total / 4 / 256), 256>>>(out);
    long long tail = (long long)out_size - total;
    if (tail > 0) tail_kernel<<<1, 32>>>(out, total, tail, expin, wexp);
}

// round 13
// speedup vs baseline: 1.3277x; 1.0210x over previous
#include <cuda_runtime.h>
#include <cstdint>

// ============================================================================
// TiLinear hybrid v8 (persistent, combine on the slack side):
//   warps 0-7  : dp4a, k-tiles [17,32), 2-stage ring, +1 la
//                tile tail: wait pfull -> read tensor partial from smem,
//                add own accs, |max|, STG combined C, arrive pfree
//   warps 8-15 : mma.sync IMMA, k-tiles [0,17), 3-stage ring, +2 la
//                tile tail: wait pfree -> STS accumulators -> arrive pfull
// The expensive combine/store/max runs in the dp4a group's measured slack;
// the tensor pipe's critical path stays clean.
// ============================================================================

#define M_DIM 8192
#define N_DIM 4096
#define K_DIM 4096
#define BITWIDTH 7

#define NTILES_TOTAL 2048
#define GRID_P 148

#define KTILES 32
#define NKT_T 17
#define NKT_D (KTILES - NKT_T)   // 15
#define TILE_BYTES 16384
#define STAGE_BYTES 32768
#define NST_T 3
#define NST_D 2
#define PB_STRIDE 130            // ints; 130 mod 32 = 2 -> conflict-free dp4a reads
#define TPOOL_OFF 0
#define DPOOL_OFF (NST_T * STAGE_BYTES)                  // 98304
#define PART_OFF  (DPOOL_OFF + NST_D * STAGE_BYTES)      // 163840
#define PART_BYTES (128 * PB_STRIDE * 4)                 // 66560
#define CTRL_OFF  (PART_OFF + PART_BYTES)                // 230400
#define SMEM_DYN  (CTRL_OFF + 128)                       // 230528

__device__ __align__(128) int8_t g_A8[(size_t)M_DIM * K_DIM];   // 32 MB
__device__ __align__(128) int8_t g_B8[(size_t)N_DIM * K_DIM];   // 16 MB
__device__ __align__(16)  int    g_C[(size_t)M_DIM * N_DIM];    // 128 MB
__device__ int g_max;

// ----------------------------------------------------------------------------
__global__ void zero_max_kernel() {
    if (threadIdx.x == 0) g_max = 0;
}

__global__ void __launch_bounds__(256) pack_a_kernel(const int* __restrict__ src) {
    unsigned i = blockIdx.x * 256u + threadIdx.x;
    unsigned lc = i & 7u;
    unsigned m  = (i >> 3) & 8191u;
    unsigned kt = i >> 16;
    const int4* s = (const int4*)(src + (size_t)m * K_DIM + kt * 128 + lc * 16);
    uint32_t w[4];
#pragma unroll
    for (int j = 0; j < 4; ++j) {
        int4 v = s[j];
        w[j] = (uint32_t)(v.x & 0xff) | ((uint32_t)(v.y & 0xff) << 8) |
               ((uint32_t)(v.z & 0xff) << 16) | ((uint32_t)(v.w & 0xff) << 24);
    }
    unsigned lr = m & 127u;
    size_t base = (size_t)(kt * 64 + (m >> 7)) * TILE_BYTES;
    size_t off  = base + lr * 128 + (((lc ^ lr) & 7u) << 4);
    *(uint4*)(g_A8 + off) = make_uint4(w[0], w[1], w[2], w[3]);
}

__global__ void __launch_bounds__(256) pack_b_kernel(const int* __restrict__ src) {
    unsigned i = blockIdx.x * 256u + threadIdx.x;
    unsigned lc = i & 7u;
    unsigned n  = (i >> 3) & 4095u;
    unsigned kt = i >> 15;
    const int4* s = (const int4*)(src + (size_t)n * K_DIM + kt * 128 + lc * 16);
    uint32_t w[4];
#pragma unroll
    for (int j = 0; j < 4; ++j) {
        int4 v = s[j];
        w[j] = (uint32_t)(v.x & 0xff) | ((uint32_t)(v.y & 0xff) << 8) |
               ((uint32_t)(v.z & 0xff) << 16) | ((uint32_t)(v.w & 0xff) << 24);
    }
    unsigned lr = n & 127u;
    size_t base = (size_t)(kt * 32 + (n >> 7)) * TILE_BYTES;
    size_t off  = base + lr * 128 + (((lc ^ lr) & 7u) << 4);
    *(uint4*)(g_B8 + off) = make_uint4(w[0], w[1], w[2], w[3]);
}

// ----------------------------------------------------------------------------
__device__ __forceinline__ void mbar_init(uint32_t a, uint32_t cnt) {
    asm volatile("mbarrier.init.shared.b64 [%0], %1;" :: "r"(a), "r"(cnt) : "memory");
}
__device__ __forceinline__ void mbar_expect_tx(uint32_t a, uint32_t bytes) {
    asm volatile("mbarrier.arrive.expect_tx.shared.b64 _, [%0], %1;"
                 :: "r"(a), "r"(bytes) : "memory");
}
__device__ __forceinline__ void mbar_arrive(uint32_t a) {
    asm volatile("mbarrier.arrive.shared.b64 _, [%0];" :: "r"(a) : "memory");
}
__device__ __forceinline__ void mbar_wait(uint32_t a, uint32_t parity) {
    asm volatile(
        "{\n\t.reg .pred P;\n\t"
        "WAIT_%=:\n\t"
        "mbarrier.try_wait.parity.acquire.cta.shared::cta.b64 P, [%0], %1, 0x989680;\n\t"
        "@P bra.uni DONE_%=;\n\t"
        "bra.uni WAIT_%=;\n\t"
        "DONE_%=:\n\t}"
        :: "r"(a), "r"(parity) : "memory");
}
__device__ __forceinline__ void bulk_g2s(uint32_t dst, const void* src,
                                         uint32_t bytes, uint32_t mbar) {
    asm volatile(
        "cp.async.bulk.shared::cluster.global.mbarrier::complete_tx::bytes "
        "[%0], [%1], %2, [%3];"
        :: "r"(dst), "l"(src), "r"(bytes), "r"(mbar) : "memory");
}
__device__ __forceinline__ uint32_t swz_off(uint32_t row, uint32_t chunk) {
    return row * 128u + (((chunk ^ row) & 7u) << 4);
}
__device__ __forceinline__ void fill_blocks(uint32_t dst, uint32_t mbar,
                                            int ablk, int bblk) {
    mbar_expect_tx(mbar, STAGE_BYTES);
    bulk_g2s(dst, g_A8 + (size_t)ablk * TILE_BYTES, TILE_BYTES, mbar);
    bulk_g2s(dst + TILE_BYTES, g_B8 + (size_t)bblk * TILE_BYTES, TILE_BYTES, mbar);
}

// ----------------------------------------------------------------------------
__global__ void __launch_bounds__(512, 1) gemm_persist_kernel() {
    extern __shared__ __align__(1024) int8_t smem[];
    const int tid  = threadIdx.x;
    const int lane = tid & 31;
    const int warp = tid >> 5;
    const int bid  = blockIdx.x;
    const int ntiles = (NTILES_TOTAL - 1 - bid) / GRID_P + 1;
    const uint32_t sbase = (uint32_t)__cvta_generic_to_shared(smem);
    const uint32_t mbT   = sbase + CTRL_OFF;        // 3 pairs
    const uint32_t mbD   = sbase + CTRL_OFF + 48;   // 2 pairs
    const uint32_t pfull = sbase + CTRL_OFF + 80;   // tensor -> dp4a (partial ready)
    const uint32_t pfree = sbase + CTRL_OFF + 88;   // dp4a -> tensor (pbuf free)
    int* pbuf = (int*)(smem + PART_OFF);

    if (tid == 0) {
#pragma unroll
        for (int s = 0; s < NST_T; ++s) {
            mbar_init(mbT + s * 16 + 0, 1);   // full (tx)
            mbar_init(mbT + s * 16 + 8, 8);   // empty (one arrive per warp)
        }
#pragma unroll
        for (int s = 0; s < NST_D; ++s) {
            mbar_init(mbD + s * 16 + 0, 1);
            mbar_init(mbD + s * 16 + 8, 8);
        }
        mbar_init(pfull, 8);   // tensor warps arrive
        mbar_init(pfree, 8);   // dp4a warps arrive
        asm volatile("fence.mbarrier_init.release.cluster;" ::: "memory");
    }
    __syncthreads();

    if (warp >= 8) {
        // ================= TENSOR GROUP: warps 8-15, k [0,17) =================
        const int tw = warp - 8;
        const int wm = tw >> 2, wn = tw & 3;
        const int total = ntiles * NKT_T;
        int cs = 0, cp = 0;
        int ps = 0, pp = 1;
        int pt = 1;            // pfree wait parity (fresh barrier passes at 1)

        auto t_fill = [&](int f) {
            int li = f / NKT_T;
            int kt = f - li * NKT_T;
            int tile = bid + li * GRID_P;
            mbar_wait(mbT + ps * 16 + 8, pp);
            fill_blocks(sbase + TPOOL_OFF + ps * STAGE_BYTES, mbT + ps * 16,
                        kt * 64 + (tile >> 5), kt * 32 + (tile & 31));
            if (++ps == NST_T) { ps = 0; pp ^= 1; }
        };

        if (tid == 256) {
            if (total > 0) t_fill(0);
            if (total > 1) t_fill(1);
        }

        for (int li = 0; li < ntiles; ++li) {
            int acc[4][4][4];
#pragma unroll
            for (int a = 0; a < 4; ++a)
#pragma unroll
                for (int b = 0; b < 4; ++b)
#pragma unroll
                    for (int c = 0; c < 4; ++c) acc[a][b][c] = 0;

#pragma unroll 1
            for (int k = 0; k < NKT_T; ++k) {
                if (tid == 256) {
                    int f = li * NKT_T + k + 2;
                    if (f < total) t_fill(f);
                }
                mbar_wait(mbT + cs * 16, cp);

                const int8_t* sa = smem + TPOOL_OFF + cs * STAGE_BYTES;
                const int8_t* sb = sa + TILE_BYTES;
#pragma unroll
                for (int ks = 0; ks < 4; ++ks) {
                    uint32_t afr[4][4];
#pragma unroll
                    for (int mi = 0; mi < 4; ++mi) {
                        int r = wm * 64 + mi * 16 + (lane & 15);
                        int c = ks * 2 + (lane >> 4);
                        uint32_t addr =
                            (uint32_t)__cvta_generic_to_shared(sa + swz_off(r, c));
                        asm volatile(
                            "ldmatrix.sync.aligned.m8n8.x4.shared.b16 "
                            "{%0,%1,%2,%3}, [%4];\n"
                            : "=r"(afr[mi][0]), "=r"(afr[mi][1]),
                              "=r"(afr[mi][2]), "=r"(afr[mi][3])
                            : "r"(addr));
                    }
                    uint32_t bfr[4][2];
#pragma unroll
                    for (int ni = 0; ni < 4; ++ni) {
                        int r = wn * 32 + ni * 8 + (lane & 7);
                        int c = ks * 2 + ((lane >> 3) & 1);
                        uint32_t addr =
                            (uint32_t)__cvta_generic_to_shared(sb + swz_off(r, c));
                        asm volatile(
                            "ldmatrix.sync.aligned.m8n8.x2.shared.b16 {%0,%1}, [%2];\n"
                            : "=r"(bfr[ni][0]), "=r"(bfr[ni][1])
                            : "r"(addr));
                    }
#pragma unroll
                    for (int mi = 0; mi < 4; ++mi)
#pragma unroll
                        for (int ni = 0; ni < 4; ++ni) {
                            asm volatile(
                                "mma.sync.aligned.m16n8k32.row.col.s32.s8.s8.s32 "
                                "{%0,%1,%2,%3}, {%4,%5,%6,%7}, {%8,%9}, {%0,%1,%2,%3};\n"
                                : "+r"(acc[mi][ni][0]), "+r"(acc[mi][ni][1]),
                                  "+r"(acc[mi][ni][2]), "+r"(acc[mi][ni][3])
                                : "r"(afr[mi][0]), "r"(afr[mi][1]),
                                  "r"(afr[mi][2]), "r"(afr[mi][3]),
                                  "r"(bfr[ni][0]), "r"(bfr[ni][1]));
                        }
                }
                __syncwarp();
                if (lane == 0) mbar_arrive(mbT + cs * 16 + 8);
                if (++cs == NST_T) { cs = 0; cp ^= 1; }
            }

            // minimal tail: park the partial in smem and move on
            mbar_wait(pfree, pt);
            pt ^= 1;
#pragma unroll
            for (int mi = 0; mi < 4; ++mi)
#pragma unroll
                for (int ni = 0; ni < 4; ++ni) {
                    int r = wm * 64 + mi * 16 + (lane >> 2);
                    int c = wn * 32 + ni * 8 + (lane & 3) * 2;
                    *(int2*)&pbuf[r * PB_STRIDE + c] =
                        make_int2(acc[mi][ni][0], acc[mi][ni][1]);
                    *(int2*)&pbuf[(r + 8) * PB_STRIDE + c] =
                        make_int2(acc[mi][ni][2], acc[mi][ni][3]);
                }
            __syncwarp();
            if (lane == 0) mbar_arrive(pfull);
        }
    } else {
        // ================= DP4A GROUP: warps 0-7, k [17,32) =================
        const int wd = warp;
        const int mg = lane >> 4;
        const int ng = lane & 15;
        const int rowA0 = 16 * wd + 8 * mg;
        const int total = ntiles * NKT_D;
        int cs = 0, cp = 0;
        int ps = 0, pp = 1;
        int pd = 0;            // pfull wait parity
        int lmax = 0;

        auto d_fill = [&](int f) {
            int li = f / NKT_D;
            int kd = f - li * NKT_D;
            int tile = bid + li * GRID_P;
            mbar_wait(mbD + ps * 16 + 8, pp);
            fill_blocks(sbase + DPOOL_OFF + ps * STAGE_BYTES, mbD + ps * 16,
                        (NKT_T + kd) * 64 + (tile >> 5),
                        (NKT_T + kd) * 32 + (tile & 31));
            if (++ps == NST_D) { ps = 0; pp ^= 1; }
        };

        if (tid == 0 && total > 0) d_fill(0);

        for (int li = 0; li < ntiles; ++li) {
            const int tile = bid + li * GRID_P;
            const int m0 = (tile >> 5) * 128;
            const int n0 = (tile & 31) * 128;

            int accD[64];
#pragma unroll
            for (int j = 0; j < 64; ++j) accD[j] = 0;

#pragma unroll 1
            for (int k = 0; k < NKT_D; ++k) {
                if (tid == 0) {
                    int f = li * NKT_D + k + 1;   // +1 lookahead (2-stage ring)
                    if (f < total) d_fill(f);
                }
                mbar_wait(mbD + cs * 16, cp);

                const int8_t* sa = smem + DPOOL_OFF + cs * STAGE_BYTES;
                const int8_t* sb = sa + TILE_BYTES;
#pragma unroll 1
                for (int cc = 0; cc < 8; ++cc) {
                    int4 a[8];
#pragma unroll
                    for (int i = 0; i < 8; ++i) {
                        int r = rowA0 + i;
                        a[i] = *(const int4*)(sa + r * 128 + (((cc ^ r) & 7) << 4));
                    }
                    const int boff = ((cc ^ ng) & 7) << 4;
                    int4 b = *(const int4*)(sb + ng * 128 + boff);
#pragma unroll
                    for (int j = 0; j < 8; ++j) {
                        int4 bn;
                        if (j < 7)
                            bn = *(const int4*)(sb + (16 * (j + 1) + ng) * 128 + boff);
#pragma unroll
                        for (int i = 0; i < 8; ++i) {
                            int t = __dp4a(a[i].x, b.x, accD[i * 8 + j]);
                            t = __dp4a(a[i].y, b.y, t);
                            t = __dp4a(a[i].z, b.z, t);
                            accD[i * 8 + j] = __dp4a(a[i].w, b.w, t);
                        }
                        if (j < 7) b = bn;
                    }
                }
                __syncwarp();
                if (lane == 0) mbar_arrive(mbD + cs * 16 + 8);
                if (++cs == NST_D) { cs = 0; cp ^= 1; }
            }

            // combine in the slack: read tensor partial, add, max, store C
            mbar_wait(pfull, pd);
            pd ^= 1;
#pragma unroll
            for (int i = 0; i < 8; ++i) {
                int r = rowA0 + i;
                const int* prow = pbuf + r * PB_STRIDE;
                int* dst = g_C + (size_t)(m0 + r) * N_DIM + n0;
#pragma unroll
                for (int j = 0; j < 8; ++j) {
                    int v = prow[16 * j + ng] + accD[i * 8 + j];
                    lmax = max(lmax, abs(v));
                    dst[16 * j + ng] = v;
                }
            }
            __syncwarp();
            if (lane == 0) mbar_arrive(pfree);
        }

#pragma unroll
        for (int o = 16; o > 0; o >>= 1)
            lmax = max(lmax, __shfl_xor_sync(0xffffffffu, lmax, o));
        if (lane == 0) atomicMax(&g_max, lmax);
    }
}

// ----------------------------------------------------------------------------
__device__ __forceinline__ int compute_eff() {
    int m = g_max;
    if (m == 0) return 0;
    float mf = (float)m;
    unsigned bits = __float_as_uint(mf);
    int e  = (int)((bits >> 23) & 0xff) - 127;
    int bw = e + ((bits & 0x7fffffu) ? 1 : 0);
    int shift = bw - BITWIDTH;
    return shift > 1 ? shift : (shift == 1 ? 2 : 0);
}

__device__ __forceinline__ int psto_one(int x, int s) {
    int rt   = x >> s;
    int prob = x & ((1 << s) - 1);
    int h    = s >> 1;
    int qp   = prob >> h;
    int prn  = prob & ((1 << h) - 1);
    if (s & 1) prn <<= 1;
    int sgn = (x > 0) - (x < 0);
    int dec = (qp <= prn) ? 0 : sgn;
    int o = rt + dec;
    o = o > 127 ? 127 : (o < -127 ? -127 : o);
    return o;
}

__global__ void __launch_bounds__(256) epilogue_kernel(float* __restrict__ out) {
    const int eff = compute_eff();
    size_t i = (size_t)blockIdx.x * blockDim.x + threadIdx.x;
    int4 v = ((const int4*)g_C)[i];
    float4 o;
    if (eff > 0) {
        o.x = (float)psto_one(v.x, eff);
        o.y = (float)psto_one(v.y, eff);
        o.z = (float)psto_one(v.z, eff);
        o.w = (float)psto_one(v.w, eff);
    } else {
        o.x = (float)(int8_t)(v.x);
        o.y = (float)(int8_t)(v.y);
        o.z = (float)(int8_t)(v.z);
        o.w = (float)(int8_t)(v.w);
    }
    ((float4*)out)[i] = o;
}

__global__ void tail_kernel(float* __restrict__ out, long long start, long long count,
                            const int* __restrict__ e1, const int* __restrict__ e2) {
    int eff = compute_eff();
    int8_t ev = (int8_t)(e1[0] + e2[0] + eff);
    for (long long i = threadIdx.x; i < count; i += blockDim.x)
        out[start + i] = (float)ev;
}

// ----------------------------------------------------------------------------
extern "C" void kernel_launch(void* const* d_in, const int* in_sizes, int n_in,
                              void* d_out, int out_size) {
    const int* act   = (const int*)d_in[0];
    const int* expin = (const int*)d_in[1];
    const int* wgt   = (const int*)d_in[2];
    const int* wexp  = (const int*)d_in[3];
    float* out = (float*)d_out;
    (void)in_sizes; (void)n_in;

    cudaFuncSetAttribute(gemm_persist_kernel,
                         cudaFuncAttributeMaxDynamicSharedMemorySize, SMEM_DYN);

    zero_max_kernel<<<1, 32>>>();
    pack_a_kernel<<<8192, 256>>>(act);
    pack_b_kernel<<<4096, 256>>>(wgt);

    gemm_persist_kernel<<<GRID_P, 512, SMEM_DYN>>>();

    long long total = (long long)M_DIM * N_DIM;           // 33554432
    epilogue_kernel<<<(int)(total / 4 / 256), 256>>>(out);
    long long tail = (long long)out_size - total;
    if (tail > 0) tail_kernel<<<1, 32>>>(out, total, tail, expin, wexp);
}